// round 1
// baseline (speedup 1.0000x reference)
#include <cuda_runtime.h>
#include <math.h>

#define BN_ 4
#define CI 256
#define CO 256
#define HN 64
#define WN 64
#define KK 9
#define EPS 1e-5f

// ---------------- scratch (device globals; no allocation) ----------------
__device__ float  g_xt[BN_*HN*WN*CI];       // x transposed to [b][y][x][c]
__device__ float  g_wofft[CI*KK*32];        // offset weights [c][tap][o(pad32)]
__device__ float  g_wt[KK*CI*CO];           // main weights  [tap][c][o]
__device__ float  g_om[BN_*HN*WN*32];       // offset conv out [m][o(pad32)]
__device__ int4   g_mbase[BN_*HN*WN*KK];    // 4 corner base indices into g_xt
__device__ float4 g_mw[BN_*HN*WN*KK];       // 4 corner weights (mask*valid premult)

// ---------------- T1: NCHW -> NHWC transpose of x ----------------
__global__ void k_transpose_x(const float* __restrict__ x) {
    __shared__ float tile[32][33];
    int b  = blockIdx.z;
    int c0 = blockIdx.y * 32;
    int p0 = blockIdx.x * 32;
    int tx = threadIdx.x, ty = threadIdx.y;
    const float* xb = x + (size_t)b * CI * HN * WN;
    #pragma unroll
    for (int j = 0; j < 32; j += 8)
        tile[ty + j][tx] = xb[(c0 + ty + j) * (HN * WN) + p0 + tx];
    __syncthreads();
    float* xtb = g_xt + (size_t)b * HN * WN * CI;
    #pragma unroll
    for (int j = 0; j < 32; j += 8)
        xtb[(p0 + ty + j) * CI + c0 + tx] = tile[tx][ty + j];
}

// ---------------- T2: weight re-layouts ----------------
__global__ void k_prep_w(const float* __restrict__ w_off, const float* __restrict__ weight) {
    int stride = gridDim.x * blockDim.x;
    int tid = blockIdx.x * blockDim.x + threadIdx.x;
    // g_wofft[(c*KK + tap)*32 + o] = w_off[o][c][tap] (o<27 else 0)
    for (int i = tid; i < CI * KK * 32; i += stride) {
        int o = i & 31; int ct = i >> 5; int tap = ct % KK; int c = ct / KK;
        g_wofft[i] = (o < 27) ? w_off[(o * CI + c) * KK + tap] : 0.f;
    }
    // g_wt[(tap*CI + c)*CO + o] = weight[o][c][tap]
    for (int i = tid; i < KK * CI * CO; i += stride) {
        int o = i & 255; int tc = i >> 8; int c = tc & 255; int tap = tc >> 8;
        g_wt[i] = weight[(o * CI + c) * KK + tap];
    }
}

// ---------------- O: offset conv as GEMM (M=16384, N=32pad, K=2304) ----------------
// one block per (b,h) row: BM=64, BN=32, BK=32; 256 threads, 2x4 register tile
__global__ __launch_bounds__(256) void k_offconv(const float* __restrict__ b_off) {
    __shared__ float As[64][33];
    __shared__ float Bs[32][33];
    int row = blockIdx.x;            // b*64+h
    int b = row >> 6, h = row & 63;
    int tid = threadIdx.x;
    int tx = tid & 7;                // n0 = tx*4
    int tm = tid >> 3;               // m0 = tm*2
    int cl = tid & 31;               // staging lane
    int mg = tid >> 5;               // staging group 0..7
    float acc[2][4];
    #pragma unroll
    for (int i = 0; i < 2; i++)
        #pragma unroll
        for (int j = 0; j < 4; j++) acc[i][j] = 0.f;

    for (int tap = 0; tap < KK; tap++) {
        int ky = tap / 3 - 1, kx = tap % 3 - 1;
        int y = h + ky;
        bool yok = (y >= 0 && y < HN);
        const float* xrow = g_xt + ((size_t)(b * HN + (yok ? y : 0)) * WN) * CI;
        for (int c0 = 0; c0 < CI; c0 += 32) {
            __syncthreads();
            #pragma unroll
            for (int j = 0; j < 8; j++) {
                int m = mg * 8 + j;
                int xx = m + kx;
                float v = 0.f;
                if (yok && xx >= 0 && xx < WN) v = xrow[xx * CI + c0 + cl];
                As[m][cl] = v;
            }
            #pragma unroll
            for (int j = 0; j < 4; j++) {
                int c = mg + 8 * j;
                Bs[c][cl] = g_wofft[((c0 + c) * KK + tap) * 32 + cl];
            }
            __syncthreads();
            #pragma unroll
            for (int kk = 0; kk < 32; kk++) {
                float a0 = As[tm * 2][kk];
                float a1 = As[tm * 2 + 1][kk];
                float b0 = Bs[kk][tx * 4 + 0];
                float b1 = Bs[kk][tx * 4 + 1];
                float b2 = Bs[kk][tx * 4 + 2];
                float b3 = Bs[kk][tx * 4 + 3];
                acc[0][0] += a0 * b0; acc[0][1] += a0 * b1;
                acc[0][2] += a0 * b2; acc[0][3] += a0 * b3;
                acc[1][0] += a1 * b0; acc[1][1] += a1 * b1;
                acc[1][2] += a1 * b2; acc[1][3] += a1 * b3;
            }
        }
    }
    int m0 = tm * 2, n0 = tx * 4;
    #pragma unroll
    for (int i = 0; i < 2; i++) {
        #pragma unroll
        for (int j = 0; j < 4; j++) {
            int n = n0 + j;
            float bo = (n < 27) ? b_off[n] : 0.f;
            g_om[(row * 64 + m0 + i) * 32 + n] = acc[i][j] + bo;
        }
    }
}

// ---------------- M: sampling metadata ----------------
__global__ void k_meta() {
    int idx = blockIdx.x * blockDim.x + threadIdx.x;
    if (idx >= BN_ * HN * WN * KK) return;
    int k = idx % KK; int m = idx / KK;
    int w = m & 63, h = (m >> 6) & 63, b = m >> 12;
    float dy = g_om[m * 32 + k];
    float dx = g_om[m * 32 + 9 + k];
    float mm = g_om[m * 32 + 18 + k];
    float mask = 1.f / (1.f + expf(-mm));
    float py = (float)h + (float)(k / 3 - 1) + dy;
    float px = (float)w + (float)(k % 3 - 1) + dx;
    float y0f = floorf(py), x0f = floorf(px);
    float ly = py - y0f, lx = px - x0f;
    int y0 = (int)y0f, x0 = (int)x0f;
    int y1 = y0 + 1, x1 = x0 + 1;
    float vy0 = (y0 >= 0 && y0 < HN) ? 1.f : 0.f;
    float vy1 = (y1 >= 0 && y1 < HN) ? 1.f : 0.f;
    float vx0 = (x0 >= 0 && x0 < WN) ? 1.f : 0.f;
    float vx1 = (x1 >= 0 && x1 < WN) ? 1.f : 0.f;
    int yc0 = min(max(y0, 0), HN - 1), yc1 = min(max(y1, 0), HN - 1);
    int xc0 = min(max(x0, 0), WN - 1), xc1 = min(max(x1, 0), WN - 1);
    float4 wv;
    wv.x = (1.f - ly) * (1.f - lx) * mask * vy0 * vx0;
    wv.y = (1.f - ly) * lx         * mask * vy0 * vx1;
    wv.z = ly * (1.f - lx)         * mask * vy1 * vx0;
    wv.w = ly * lx                 * mask * vy1 * vx1;
    int bb = b * HN * WN;
    int4 bv;
    bv.x = (bb + yc0 * WN + xc0) * CI;
    bv.y = (bb + yc0 * WN + xc1) * CI;
    bv.z = (bb + yc1 * WN + xc0) * CI;
    bv.w = (bb + yc1 * WN + xc1) * CI;
    g_mbase[idx] = bv;
    g_mw[idx] = wv;
}

// ---------------- G: fused sample + GEMM + BN + ReLU ----------------
// BM=128, BN=64, BK=32; 256 threads, 8x4 register tile
__global__ __launch_bounds__(256) void k_main(const float* __restrict__ bias,
                                              const float* __restrict__ gamma,
                                              const float* __restrict__ beta,
                                              const float* __restrict__ rmean,
                                              const float* __restrict__ rvar,
                                              float* __restrict__ out) {
    __shared__ float As[128][33];
    __shared__ __align__(16) float Bs[32][68];
    __shared__ int4   SB[128];
    __shared__ float4 SWt[128];
    int m_base = blockIdx.x * 128;
    int n_base = blockIdx.y * 64;
    int tid = threadIdx.x;
    int tn = tid & 15;          // n0 = tn*4
    int tm = tid >> 4;          // m0 = tm*8
    int cl = tid & 31;          // staging lane
    int mg = tid >> 5;          // staging group 0..7
    float acc[8][4];
    #pragma unroll
    for (int i = 0; i < 8; i++)
        #pragma unroll
        for (int j = 0; j < 4; j++) acc[i][j] = 0.f;

    for (int tap = 0; tap < KK; tap++) {
        __syncthreads();
        if (tid < 128) SB[tid] = g_mbase[(m_base + tid) * KK + tap];
        else           SWt[tid - 128] = g_mw[(m_base + tid - 128) * KK + tap];
        for (int c0 = 0; c0 < CI; c0 += 32) {
            __syncthreads();
            #pragma unroll
            for (int j = 0; j < 16; j++) {
                int m = mg * 16 + j;
                int4 bs = SB[m];
                float4 ws = SWt[m];
                int c = c0 + cl;
                float v = ws.x * g_xt[bs.x + c] + ws.y * g_xt[bs.y + c]
                        + ws.z * g_xt[bs.z + c] + ws.w * g_xt[bs.w + c];
                As[m][cl] = v;
            }
            {
                int n = tid & 63;
                int cg = tid >> 6;  // 0..3
                #pragma unroll
                for (int j = 0; j < 8; j++) {
                    int c = cg + 4 * j;
                    Bs[c][n] = g_wt[(tap * CI + c0 + c) * CO + n_base + n];
                }
            }
            __syncthreads();
            #pragma unroll
            for (int kk = 0; kk < 32; kk++) {
                float a[8];
                #pragma unroll
                for (int i = 0; i < 8; i++) a[i] = As[tm * 8 + i][kk];
                float4 bb = *reinterpret_cast<float4*>(&Bs[kk][tn * 4]);
                #pragma unroll
                for (int i = 0; i < 8; i++) {
                    acc[i][0] += a[i] * bb.x;
                    acc[i][1] += a[i] * bb.y;
                    acc[i][2] += a[i] * bb.z;
                    acc[i][3] += a[i] * bb.w;
                }
            }
        }
    }
    // epilogue: bias + BN (eval) + ReLU, write NCHW
    float scale[4], shift[4], bs4[4];
    #pragma unroll
    for (int j = 0; j < 4; j++) {
        int o = n_base + tn * 4 + j;
        float inv = gamma[o] * rsqrtf(rvar[o] + EPS);
        scale[j] = inv;
        shift[j] = beta[o] - rmean[o] * inv;
        bs4[j] = bias[o];
    }
    #pragma unroll
    for (int i = 0; i < 8; i++) {
        int m = m_base + tm * 8 + i;
        int b = m >> 12, h = (m >> 6) & 63, w = m & 63;
        #pragma unroll
        for (int j = 0; j < 4; j++) {
            int o = n_base + tn * 4 + j;
            float v = (acc[i][j] + bs4[j]) * scale[j] + shift[j];
            out[((b * CO + o) * HN + h) * WN + w] = fmaxf(v, 0.f);
        }
    }
}

// ---------------- launch ----------------
extern "C" void kernel_launch(void* const* d_in, const int* in_sizes, int n_in,
                              void* d_out, int out_size) {
    const float* x      = (const float*)d_in[0];
    const float* w_off  = (const float*)d_in[1];
    const float* b_off  = (const float*)d_in[2];
    const float* weight = (const float*)d_in[3];
    const float* bias   = (const float*)d_in[4];
    const float* gamma  = (const float*)d_in[5];
    const float* beta   = (const float*)d_in[6];
    const float* rmean  = (const float*)d_in[7];
    const float* rvar   = (const float*)d_in[8];
    float* out = (float*)d_out;

    dim3 tgrid(HN * WN / 32, CI / 32, BN_);
    k_transpose_x<<<tgrid, dim3(32, 8)>>>(x);
    k_prep_w<<<256, 256>>>(w_off, weight);
    k_offconv<<<BN_ * HN, 256>>>(b_off);
    k_meta<<<(BN_ * HN * WN * KK + 255) / 256, 256>>>();
    k_main<<<dim3(BN_ * HN * WN / 128, CO / 64), 256>>>(bias, gamma, beta, rmean, rvar, out);
}

// round 3
// speedup vs baseline: 1.9670x; 1.9670x over previous
#include <cuda_runtime.h>
#include <cuda_bf16.h>
#include <math.h>

#define BN_ 4
#define CI 256
#define CO 256
#define HN 64
#define WN 64
#define KK 9
#define EPS 1e-5f

// ---------------- scratch (device globals; no allocation) ----------------
__device__ float  g_xt[BN_*HN*WN*CI];       // x transposed to [b][y][x][c]
__device__ float  g_wofft[CI*KK*32];        // offset weights [c][tap][o(pad32)]
__device__ __nv_bfloat16 g_wtb_hi[KK*CO*CI]; // main weights split hi [tap][o][c]
__device__ __nv_bfloat16 g_wtb_lo[KK*CO*CI]; // main weights split lo [tap][o][c]
__device__ float  g_om[BN_*HN*WN*32];       // offset conv out [m][o(pad32)]
__device__ int4   g_mbase[BN_*HN*WN*KK];    // 4 corner base indices into g_xt
__device__ float4 g_mw[BN_*HN*WN*KK];       // 4 corner weights (mask*valid premult)

static __device__ __forceinline__ unsigned smem_u32(const void* p) {
    return (unsigned)__cvta_generic_to_shared(p);
}

static __device__ __forceinline__ void mma_bf16(float* c, const unsigned* a, const unsigned* b) {
    asm volatile(
        "mma.sync.aligned.m16n8k16.row.col.f32.bf16.bf16.f32 "
        "{%0,%1,%2,%3}, {%4,%5,%6,%7}, {%8,%9}, {%0,%1,%2,%3};"
        : "+f"(c[0]), "+f"(c[1]), "+f"(c[2]), "+f"(c[3])
        : "r"(a[0]), "r"(a[1]), "r"(a[2]), "r"(a[3]), "r"(b[0]), "r"(b[1]));
}

static __device__ __forceinline__ void ldmat_x4(unsigned* r, unsigned addr) {
    asm volatile("ldmatrix.sync.aligned.m8n8.x4.shared.b16 {%0,%1,%2,%3}, [%4];"
                 : "=r"(r[0]), "=r"(r[1]), "=r"(r[2]), "=r"(r[3]) : "r"(addr));
}

// ---------------- T1: NCHW -> NHWC transpose of x ----------------
__global__ void k_transpose_x(const float* __restrict__ x) {
    __shared__ float tile[32][33];
    int b  = blockIdx.z;
    int c0 = blockIdx.y * 32;
    int p0 = blockIdx.x * 32;
    int tx = threadIdx.x, ty = threadIdx.y;
    const float* xb = x + (size_t)b * CI * HN * WN;
    #pragma unroll
    for (int j = 0; j < 32; j += 8)
        tile[ty + j][tx] = xb[(c0 + ty + j) * (HN * WN) + p0 + tx];
    __syncthreads();
    float* xtb = g_xt + (size_t)b * HN * WN * CI;
    #pragma unroll
    for (int j = 0; j < 32; j += 8)
        xtb[(p0 + ty + j) * CI + c0 + tx] = tile[tx][ty + j];
}

// ---------------- T2: weight re-layouts (+ bf16 hi/lo split) ----------------
__global__ void k_prep_w(const float* __restrict__ w_off, const float* __restrict__ weight) {
    int stride = gridDim.x * blockDim.x;
    int tid = blockIdx.x * blockDim.x + threadIdx.x;
    // g_wofft[(c*KK + tap)*32 + o] = w_off[o][c][tap] (o<27 else 0)
    for (int i = tid; i < CI * KK * 32; i += stride) {
        int o = i & 31; int ct = i >> 5; int tap = ct % KK; int c = ct / KK;
        g_wofft[i] = (o < 27) ? w_off[(o * CI + c) * KK + tap] : 0.f;
    }
    // g_wtb_{hi,lo}[(tap*CO + o)*CI + c] = split(weight[o][c][tap])
    for (int i = tid; i < KK * CO * CI; i += stride) {
        int c = i & 255; int to = i >> 8; int o = to & 255; int tap = to >> 8;
        float w = weight[(o * CI + c) * KK + tap];
        __nv_bfloat16 hi = __float2bfloat16(w);
        float lo_f = w - __bfloat162float(hi);
        g_wtb_hi[i] = hi;
        g_wtb_lo[i] = __float2bfloat16(lo_f);
    }
}

// ---------------- O: offset conv as GEMM (M=16384, N=32pad, K=2304) ----------------
__global__ __launch_bounds__(256) void k_offconv(const float* __restrict__ b_off) {
    __shared__ float As[64][33];
    __shared__ float Bs[32][33];
    int row = blockIdx.x;            // b*64+h
    int b = row >> 6, h = row & 63;
    int tid = threadIdx.x;
    int tx = tid & 7;                // n0 = tx*4
    int tm = tid >> 3;               // m0 = tm*2
    int cl = tid & 31;               // staging lane
    int mg = tid >> 5;               // staging group 0..7
    float acc[2][4];
    #pragma unroll
    for (int i = 0; i < 2; i++)
        #pragma unroll
        for (int j = 0; j < 4; j++) acc[i][j] = 0.f;

    for (int tap = 0; tap < KK; tap++) {
        int ky = tap / 3 - 1, kx = tap % 3 - 1;
        int y = h + ky;
        bool yok = (y >= 0 && y < HN);
        const float* xrow = g_xt + ((size_t)(b * HN + (yok ? y : 0)) * WN) * CI;
        for (int c0 = 0; c0 < CI; c0 += 32) {
            __syncthreads();
            #pragma unroll
            for (int j = 0; j < 8; j++) {
                int m = mg * 8 + j;
                int xx = m + kx;
                float v = 0.f;
                if (yok && xx >= 0 && xx < WN) v = xrow[xx * CI + c0 + cl];
                As[m][cl] = v;
            }
            #pragma unroll
            for (int j = 0; j < 4; j++) {
                int c = mg + 8 * j;
                Bs[c][cl] = g_wofft[((c0 + c) * KK + tap) * 32 + cl];
            }
            __syncthreads();
            #pragma unroll
            for (int kk = 0; kk < 32; kk++) {
                float a0 = As[tm * 2][kk];
                float a1 = As[tm * 2 + 1][kk];
                float b0 = Bs[kk][tx * 4 + 0];
                float b1 = Bs[kk][tx * 4 + 1];
                float b2 = Bs[kk][tx * 4 + 2];
                float b3 = Bs[kk][tx * 4 + 3];
                acc[0][0] += a0 * b0; acc[0][1] += a0 * b1;
                acc[0][2] += a0 * b2; acc[0][3] += a0 * b3;
                acc[1][0] += a1 * b0; acc[1][1] += a1 * b1;
                acc[1][2] += a1 * b2; acc[1][3] += a1 * b3;
            }
        }
    }
    int m0 = tm * 2, n0 = tx * 4;
    #pragma unroll
    for (int i = 0; i < 2; i++) {
        #pragma unroll
        for (int j = 0; j < 4; j++) {
            int n = n0 + j;
            float bo = (n < 27) ? b_off[n] : 0.f;
            g_om[(row * 64 + m0 + i) * 32 + n] = acc[i][j] + bo;
        }
    }
}

// ---------------- M: sampling metadata ----------------
__global__ void k_meta() {
    int idx = blockIdx.x * blockDim.x + threadIdx.x;
    if (idx >= BN_ * HN * WN * KK) return;
    int k = idx % KK; int m = idx / KK;
    int w = m & 63, h = (m >> 6) & 63, b = m >> 12;
    float dy = g_om[m * 32 + k];
    float dx = g_om[m * 32 + 9 + k];
    float mm = g_om[m * 32 + 18 + k];
    float mask = 1.f / (1.f + expf(-mm));
    float py = (float)h + (float)(k / 3 - 1) + dy;
    float px = (float)w + (float)(k % 3 - 1) + dx;
    float y0f = floorf(py), x0f = floorf(px);
    float ly = py - y0f, lx = px - x0f;
    int y0 = (int)y0f, x0 = (int)x0f;
    int y1 = y0 + 1, x1 = x0 + 1;
    float vy0 = (y0 >= 0 && y0 < HN) ? 1.f : 0.f;
    float vy1 = (y1 >= 0 && y1 < HN) ? 1.f : 0.f;
    float vx0 = (x0 >= 0 && x0 < WN) ? 1.f : 0.f;
    float vx1 = (x1 >= 0 && x1 < WN) ? 1.f : 0.f;
    int yc0 = min(max(y0, 0), HN - 1), yc1 = min(max(y1, 0), HN - 1);
    int xc0 = min(max(x0, 0), WN - 1), xc1 = min(max(x1, 0), WN - 1);
    float4 wv;
    wv.x = (1.f - ly) * (1.f - lx) * mask * vy0 * vx0;
    wv.y = (1.f - ly) * lx         * mask * vy0 * vx1;
    wv.z = ly * (1.f - lx)         * mask * vy1 * vx0;
    wv.w = ly * lx                 * mask * vy1 * vx1;
    int bb = b * HN * WN;
    int4 bv;
    bv.x = (bb + yc0 * WN + xc0) * CI;
    bv.y = (bb + yc0 * WN + xc1) * CI;
    bv.z = (bb + yc1 * WN + xc0) * CI;
    bv.w = (bb + yc1 * WN + xc1) * CI;
    g_mbase[idx] = bv;
    g_mw[idx] = wv;
}

// ---------------- G: fused sample + bf16x3 tensor GEMM + BN + ReLU ----------------
// BM=128, BN=128, BK=32; 256 threads = 8 warps; warp tile 32x64 (m16n8k16)
#define PAD 40   // bf16 elements per smem row (32 data + 8 pad) -> 80B rows, conflict-free

__global__ __launch_bounds__(256) void k_main(const float* __restrict__ bias,
                                              const float* __restrict__ gamma,
                                              const float* __restrict__ beta,
                                              const float* __restrict__ rmean,
                                              const float* __restrict__ rvar,
                                              float* __restrict__ out) {
    __shared__ __align__(16) __nv_bfloat16 As_hi[128 * PAD];
    __shared__ __align__(16) __nv_bfloat16 As_lo[128 * PAD];
    __shared__ __align__(16) __nv_bfloat16 Bs_hi[128 * PAD];
    __shared__ __align__(16) __nv_bfloat16 Bs_lo[128 * PAD];
    __shared__ int4   SB[128];
    __shared__ float4 SW[128];
    __shared__ float  s_scale[128], s_shift[128], s_bias[128];

    int m_base = blockIdx.x * 128;
    int n_base = blockIdx.y * 128;
    int tid = threadIdx.x;
    int lane = tid & 31;
    int wid = tid >> 5;
    int wm = wid & 3;          // m-warp 0..3 (32 rows each)
    int wn = wid >> 2;         // n-warp 0..1 (64 cols each)

    // per-block BN/bias LUT
    if (tid < 128) {
        int o = n_base + tid;
        float inv = gamma[o] * rsqrtf(rvar[o] + EPS);
        s_scale[tid] = inv;
        s_shift[tid] = beta[o] - rmean[o] * inv;
        s_bias[tid]  = bias[o];
    }

    float acc[2][8][4];
    #pragma unroll
    for (int i = 0; i < 2; i++)
        #pragma unroll
        for (int j = 0; j < 8; j++)
            #pragma unroll
            for (int q = 0; q < 4; q++) acc[i][j][q] = 0.f;

    // precompute ldmatrix lane addresses (A frags): row = lane&15, koff = (lane>>4)*8
    unsigned a_row = (unsigned)(lane & 15);
    unsigned a_koff = (unsigned)((lane >> 4) * 8);
    unsigned as_hi_base = smem_u32(As_hi);
    unsigned as_lo_base = smem_u32(As_lo);

    for (int tap = 0; tap < KK; tap++) {
        __syncthreads();
        if (tid < 128) SB[tid] = g_mbase[(m_base + tid) * KK + tap];
        else           SW[tid - 128] = g_mw[(m_base + tid - 128) * KK + tap];
        const __nv_bfloat16* wb_hi = g_wtb_hi + (size_t)(tap * CO + n_base) * CI;
        const __nv_bfloat16* wb_lo = g_wtb_lo + (size_t)(tap * CO + n_base) * CI;

        for (int c0 = 0; c0 < CI; c0 += 32) {
            __syncthreads();
            // ---- build A tile: 128 m x 32 c, via float4 gather + split ----
            #pragma unroll
            for (int j = 0; j < 4; j++) {
                int task = tid + 256 * j;           // 0..1023
                int q = task & 7;                   // c-quad 0..7
                int m = task >> 3;                  // 0..127
                int4 bs = SB[m];
                float4 ws = SW[m];
                int c = c0 + q * 4;
                float4 p0 = *(const float4*)&g_xt[bs.x + c];
                float4 p1 = *(const float4*)&g_xt[bs.y + c];
                float4 p2 = *(const float4*)&g_xt[bs.z + c];
                float4 p3 = *(const float4*)&g_xt[bs.w + c];
                float v0 = ws.x * p0.x + ws.y * p1.x + ws.z * p2.x + ws.w * p3.x;
                float v1 = ws.x * p0.y + ws.y * p1.y + ws.z * p2.y + ws.w * p3.y;
                float v2 = ws.x * p0.z + ws.y * p1.z + ws.z * p2.z + ws.w * p3.z;
                float v3 = ws.x * p0.w + ws.y * p1.w + ws.z * p2.w + ws.w * p3.w;
                __nv_bfloat16 h0 = __float2bfloat16(v0);
                __nv_bfloat16 h1 = __float2bfloat16(v1);
                __nv_bfloat16 h2 = __float2bfloat16(v2);
                __nv_bfloat16 h3 = __float2bfloat16(v3);
                __nv_bfloat162 hp0; hp0.x = h0; hp0.y = h1;
                __nv_bfloat162 hp1; hp1.x = h2; hp1.y = h3;
                __nv_bfloat162 lp0;
                lp0.x = __float2bfloat16(v0 - __bfloat162float(h0));
                lp0.y = __float2bfloat16(v1 - __bfloat162float(h1));
                __nv_bfloat162 lp1;
                lp1.x = __float2bfloat16(v2 - __bfloat162float(h2));
                lp1.y = __float2bfloat16(v3 - __bfloat162float(h3));
                int off = m * PAD + q * 4;
                *(__nv_bfloat162*)&As_hi[off]     = hp0;
                *(__nv_bfloat162*)&As_hi[off + 2] = hp1;
                *(__nv_bfloat162*)&As_lo[off]     = lp0;
                *(__nv_bfloat162*)&As_lo[off + 2] = lp1;
            }
            // ---- load B tile: 128 n x 32 c (n-major rows) ----
            #pragma unroll
            for (int j = 0; j < 2; j++) {
                int idx = tid + 256 * j;            // 0..511
                int n = idx >> 2;                   // 0..127
                int part = idx & 3;                 // 8 bf16 each
                size_t src = (size_t)n * CI + c0 + part * 8;
                uint4 vh = *(const uint4*)&wb_hi[src];
                uint4 vl = *(const uint4*)&wb_lo[src];
                *(uint4*)&Bs_hi[n * PAD + part * 8] = vh;
                *(uint4*)&Bs_lo[n * PAD + part * 8] = vl;
            }
            __syncthreads();
            // ---- mma: 2 k16 steps ----
            #pragma unroll
            for (int ks = 0; ks < 2; ks++) {
                unsigned ahi[2][4], alo[2][4];
                #pragma unroll
                for (int mf = 0; mf < 2; mf++) {
                    unsigned row = (unsigned)(wm * 32 + mf * 16) + a_row;
                    unsigned boff = row * (PAD * 2) + (ks * 16 + a_koff) * 2;
                    ldmat_x4(ahi[mf], as_hi_base + boff);
                    ldmat_x4(alo[mf], as_lo_base + boff);
                }
                #pragma unroll
                for (int nf = 0; nf < 8; nf++) {
                    int n = wn * 64 + nf * 8 + (lane >> 2);
                    int k0 = ks * 16 + (lane & 3) * 2;
                    unsigned bhi[2], blo[2];
                    bhi[0] = *(const unsigned*)&Bs_hi[n * PAD + k0];
                    bhi[1] = *(const unsigned*)&Bs_hi[n * PAD + k0 + 8];
                    blo[0] = *(const unsigned*)&Bs_lo[n * PAD + k0];
                    blo[1] = *(const unsigned*)&Bs_lo[n * PAD + k0 + 8];
                    #pragma unroll
                    for (int mf = 0; mf < 2; mf++) {
                        mma_bf16(acc[mf][nf], ahi[mf], bhi);
                        mma_bf16(acc[mf][nf], ahi[mf], blo);
                        mma_bf16(acc[mf][nf], alo[mf], bhi);
                    }
                }
            }
        }
    }

    // ---- epilogue: bias + BN + ReLU, write NCHW ----
    int g = lane >> 2;
    int cq = (lane & 3) * 2;
    #pragma unroll
    for (int mf = 0; mf < 2; mf++) {
        int row0 = m_base + wm * 32 + mf * 16 + g;
        #pragma unroll
        for (int half = 0; half < 2; half++) {
            int m = row0 + half * 8;
            int b = m >> 12, h = (m >> 6) & 63, w = m & 63;
            float* orow = out + ((size_t)b * CO * HN + h) * WN + w;
            #pragma unroll
            for (int nf = 0; nf < 8; nf++) {
                int nl0 = wn * 64 + nf * 8 + cq;      // local col 0
                #pragma unroll
                for (int j = 0; j < 2; j++) {
                    int nl = nl0 + j;
                    int o = n_base + nl;
                    float v = (acc[mf][nf][half * 2 + j] + s_bias[nl]) * s_scale[nl] + s_shift[nl];
                    orow[(size_t)o * HN * WN] = fmaxf(v, 0.f);
                }
            }
        }
    }
}

// ---------------- launch ----------------
extern "C" void kernel_launch(void* const* d_in, const int* in_sizes, int n_in,
                              void* d_out, int out_size) {
    const float* x      = (const float*)d_in[0];
    const float* w_off  = (const float*)d_in[1];
    const float* b_off  = (const float*)d_in[2];
    const float* weight = (const float*)d_in[3];
    const float* bias   = (const float*)d_in[4];
    const float* gamma  = (const float*)d_in[5];
    const float* beta   = (const float*)d_in[6];
    const float* rmean  = (const float*)d_in[7];
    const float* rvar   = (const float*)d_in[8];
    float* out = (float*)d_out;

    dim3 tgrid(HN * WN / 32, CI / 32, BN_);
    k_transpose_x<<<tgrid, dim3(32, 8)>>>(x);
    k_prep_w<<<256, 256>>>(w_off, weight);
    k_offconv<<<BN_ * HN, 256>>>(b_off);
    k_meta<<<(BN_ * HN * WN * KK + 255) / 256, 256>>>();
    k_main<<<dim3(BN_ * HN * WN / 128, CO / 128), 256>>>(bias, gamma, beta, rmean, rvar, out);
}

// round 4
// speedup vs baseline: 4.0381x; 2.0530x over previous
#include <cuda_runtime.h>
#include <cuda_fp16.h>
#include <math.h>

#define BN_ 4
#define CI 256
#define CO 256
#define HN 64
#define WN 64
#define KK 9
#define EPS 1e-5f

// ---------------- scratch (device globals; no allocation) ----------------
__device__ float  g_xt[BN_*HN*WN*CI];       // x transposed to [b][y][x][c]
__device__ __half g_woffh[KK*32*CI];        // offset weights fp16 [tap][o(pad32)][c]
__device__ __half g_wth[KK*CO*CI];          // main weights fp16 [tap][o][c]
__device__ float  g_om[BN_*HN*WN*32];       // offset conv out [m][o(pad32)]
__device__ int4   g_mbase[BN_*HN*WN*KK];    // 4 corner base indices into g_xt
__device__ float4 g_mw[BN_*HN*WN*KK];       // 4 corner weights (mask*valid premult)

static __device__ __forceinline__ unsigned smem_u32(const void* p) {
    return (unsigned)__cvta_generic_to_shared(p);
}

static __device__ __forceinline__ void mma_f16(float* c, const unsigned* a, const unsigned* b) {
    asm volatile(
        "mma.sync.aligned.m16n8k16.row.col.f32.f16.f16.f32 "
        "{%0,%1,%2,%3}, {%4,%5,%6,%7}, {%8,%9}, {%0,%1,%2,%3};"
        : "+f"(c[0]), "+f"(c[1]), "+f"(c[2]), "+f"(c[3])
        : "r"(a[0]), "r"(a[1]), "r"(a[2]), "r"(a[3]), "r"(b[0]), "r"(b[1]));
}

static __device__ __forceinline__ void ldmat_x4(unsigned* r, unsigned addr) {
    asm volatile("ldmatrix.sync.aligned.m8n8.x4.shared.b16 {%0,%1,%2,%3}, [%4];"
                 : "=r"(r[0]), "=r"(r[1]), "=r"(r[2]), "=r"(r[3]) : "r"(addr));
}

// ---------------- T1: NCHW -> NHWC transpose of x ----------------
__global__ void k_transpose_x(const float* __restrict__ x) {
    __shared__ float tile[32][33];
    int b  = blockIdx.z;
    int c0 = blockIdx.y * 32;
    int p0 = blockIdx.x * 32;
    int tx = threadIdx.x, ty = threadIdx.y;
    const float* xb = x + (size_t)b * CI * HN * WN;
    #pragma unroll
    for (int j = 0; j < 32; j += 8)
        tile[ty + j][tx] = xb[(c0 + ty + j) * (HN * WN) + p0 + tx];
    __syncthreads();
    float* xtb = g_xt + (size_t)b * HN * WN * CI;
    #pragma unroll
    for (int j = 0; j < 32; j += 8)
        xtb[(p0 + ty + j) * CI + c0 + tx] = tile[tx][ty + j];
}

// ---------------- T2: weight re-layouts (fp16) ----------------
__global__ void k_prep_w(const float* __restrict__ w_off, const float* __restrict__ weight) {
    int stride = gridDim.x * blockDim.x;
    int tid = blockIdx.x * blockDim.x + threadIdx.x;
    // g_woffh[(tap*32 + o)*CI + c] = w_off[o][c][tap] (o<27 else 0)
    for (int i = tid; i < KK * 32 * CI; i += stride) {
        int c = i & 255; int to = i >> 8; int o = to & 31; int tap = to >> 5;
        float v = (o < 27) ? w_off[(o * CI + c) * KK + tap] : 0.f;
        g_woffh[i] = __float2half_rn(v);
    }
    // g_wth[(tap*CO + o)*CI + c] = weight[o][c][tap]
    for (int i = tid; i < KK * CO * CI; i += stride) {
        int c = i & 255; int to = i >> 8; int o = to & 255; int tap = to >> 8;
        g_wth[i] = __float2half_rn(weight[(o * CI + c) * KK + tap]);
    }
}

// ---------------- O: offset conv, fp16 tensor GEMM (BM=64, BN=32, BK=32) ----------------
#define PAD 40   // fp16 elements per smem row (32 data + 8 pad) -> 80B rows, conflict-free

__global__ __launch_bounds__(256) void k_offconv(const float* __restrict__ b_off) {
    __shared__ __align__(16) __half As[64 * PAD];
    __shared__ __align__(16) __half Bs[32 * PAD];
    int row = blockIdx.x;            // b*64+h
    int b = row >> 6, h = row & 63;
    int tid = threadIdx.x;
    int lane = tid & 31;
    int wid = tid >> 5;
    int wm = wid & 3;                // 16 m-rows each
    int wn = wid >> 2;               // 16 n-cols each

    float acc[2][4];
    #pragma unroll
    for (int i = 0; i < 2; i++)
        #pragma unroll
        for (int j = 0; j < 4; j++) acc[i][j] = 0.f;

    unsigned a_row = (unsigned)(lane & 15);
    unsigned a_koff = (unsigned)((lane >> 4) * 8);
    unsigned as_base = smem_u32(As);

    for (int tap = 0; tap < KK; tap++) {
        int ky = tap / 3 - 1, kx = tap % 3 - 1;
        int y = h + ky;
        bool yok = (y >= 0 && y < HN);
        const float* xrow = g_xt + ((size_t)(b * HN + (yok ? y : 0)) * WN) * CI;
        for (int c0 = 0; c0 < CI; c0 += 32) {
            __syncthreads();
            // A: 64 m x 32 c (shifted window), 512 tasks
            #pragma unroll
            for (int j = 0; j < 2; j++) {
                int task = tid + 256 * j;
                int q = task & 7;
                int m = task >> 3;
                int xx = m + kx;
                float4 p = make_float4(0.f, 0.f, 0.f, 0.f);
                if (yok && xx >= 0 && xx < WN)
                    p = *(const float4*)&xrow[xx * CI + c0 + q * 4];
                __half2 h0; h0.x = __float2half_rn(p.x); h0.y = __float2half_rn(p.y);
                __half2 h1; h1.x = __float2half_rn(p.z); h1.y = __float2half_rn(p.w);
                uint2 pk; pk.x = *(unsigned*)&h0; pk.y = *(unsigned*)&h1;
                *(uint2*)&As[m * PAD + q * 4] = pk;
            }
            // B: 32 n x 32 c
            if (tid < 128) {
                int n = tid >> 2, part = tid & 3;
                uint4 v = *(const uint4*)&g_woffh[((size_t)(tap * 32 + n)) * CI + c0 + part * 8];
                *(uint4*)&Bs[n * PAD + part * 8] = v;
            }
            __syncthreads();
            #pragma unroll
            for (int ks = 0; ks < 2; ks++) {
                unsigned a[4];
                unsigned boff = (wm * 16 + a_row) * (PAD * 2) + (ks * 16 + a_koff) * 2;
                ldmat_x4(a, as_base + boff);
                #pragma unroll
                for (int nf = 0; nf < 2; nf++) {
                    int n = wn * 16 + nf * 8 + (lane >> 2);
                    int k0 = ks * 16 + (lane & 3) * 2;
                    unsigned bb[2];
                    bb[0] = *(const unsigned*)&Bs[n * PAD + k0];
                    bb[1] = *(const unsigned*)&Bs[n * PAD + k0 + 8];
                    mma_f16(acc[nf], a, bb);
                }
            }
        }
    }
    // epilogue -> g_om
    int g = lane >> 2;
    int cq = (lane & 3) * 2;
    #pragma unroll
    for (int nf = 0; nf < 2; nf++) {
        #pragma unroll
        for (int half = 0; half < 2; half++) {
            int m = wm * 16 + half * 8 + g;
            #pragma unroll
            for (int j = 0; j < 2; j++) {
                int n = wn * 16 + nf * 8 + cq + j;
                float bo = (n < 27) ? b_off[n] : 0.f;
                g_om[(row * 64 + m) * 32 + n] = acc[nf][half * 2 + j] + bo;
            }
        }
    }
}

// ---------------- M: sampling metadata ----------------
__global__ void k_meta() {
    int idx = blockIdx.x * blockDim.x + threadIdx.x;
    if (idx >= BN_ * HN * WN * KK) return;
    int k = idx % KK; int m = idx / KK;
    int w = m & 63, h = (m >> 6) & 63, b = m >> 12;
    float dy = g_om[m * 32 + k];
    float dx = g_om[m * 32 + 9 + k];
    float mm = g_om[m * 32 + 18 + k];
    float mask = 1.f / (1.f + expf(-mm));
    float py = (float)h + (float)(k / 3 - 1) + dy;
    float px = (float)w + (float)(k % 3 - 1) + dx;
    float y0f = floorf(py), x0f = floorf(px);
    float ly = py - y0f, lx = px - x0f;
    int y0 = (int)y0f, x0 = (int)x0f;
    int y1 = y0 + 1, x1 = x0 + 1;
    float vy0 = (y0 >= 0 && y0 < HN) ? 1.f : 0.f;
    float vy1 = (y1 >= 0 && y1 < HN) ? 1.f : 0.f;
    float vx0 = (x0 >= 0 && x0 < WN) ? 1.f : 0.f;
    float vx1 = (x1 >= 0 && x1 < WN) ? 1.f : 0.f;
    int yc0 = min(max(y0, 0), HN - 1), yc1 = min(max(y1, 0), HN - 1);
    int xc0 = min(max(x0, 0), WN - 1), xc1 = min(max(x1, 0), WN - 1);
    float4 wv;
    wv.x = (1.f - ly) * (1.f - lx) * mask * vy0 * vx0;
    wv.y = (1.f - ly) * lx         * mask * vy0 * vx1;
    wv.z = ly * (1.f - lx)         * mask * vy1 * vx0;
    wv.w = ly * lx                 * mask * vy1 * vx1;
    int bb = b * HN * WN;
    int4 bv;
    bv.x = (bb + yc0 * WN + xc0) * CI;
    bv.y = (bb + yc0 * WN + xc1) * CI;
    bv.z = (bb + yc1 * WN + xc0) * CI;
    bv.w = (bb + yc1 * WN + xc1) * CI;
    g_mbase[idx] = bv;
    g_mw[idx] = wv;
}

// ---------------- G: fused sample + fp16x2 tensor GEMM + BN + ReLU ----------------
// BM=128, BN=128, BK=32; 256 threads = 8 warps; warp tile 32x64 (m16n8k16)
__global__ __launch_bounds__(256, 2) void k_main(const float* __restrict__ bias,
                                              const float* __restrict__ gamma,
                                              const float* __restrict__ beta,
                                              const float* __restrict__ rmean,
                                              const float* __restrict__ rvar,
                                              float* __restrict__ out) {
    __shared__ __align__(16) __half As_hi[128 * PAD];
    __shared__ __align__(16) __half As_lo[128 * PAD];
    __shared__ __align__(16) __half Bs[128 * PAD];
    __shared__ int4   SB[128];
    __shared__ float4 SW[128];
    __shared__ float  s_scale[128], s_shift[128];

    int m_base = blockIdx.x * 128;
    int n_base = blockIdx.y * 128;
    int tid = threadIdx.x;
    int lane = tid & 31;
    int wid = tid >> 5;
    int wm = wid & 3;          // m-warp 0..3 (32 rows each)
    int wn = wid >> 2;         // n-warp 0..1 (64 cols each)

    // per-block BN LUT (bias folded into shift)
    if (tid < 128) {
        int o = n_base + tid;
        float inv = gamma[o] * rsqrtf(rvar[o] + EPS);
        s_scale[tid] = inv;
        s_shift[tid] = beta[o] - rmean[o] * inv + bias[o] * inv;
    }

    float acc[2][8][4];
    #pragma unroll
    for (int i = 0; i < 2; i++)
        #pragma unroll
        for (int j = 0; j < 8; j++)
            #pragma unroll
            for (int q = 0; q < 4; q++) acc[i][j][q] = 0.f;

    unsigned a_row = (unsigned)(lane & 15);
    unsigned a_koff = (unsigned)((lane >> 4) * 8);
    unsigned as_hi_base = smem_u32(As_hi);
    unsigned as_lo_base = smem_u32(As_lo);

    for (int tap = 0; tap < KK; tap++) {
        __syncthreads();
        if (tid < 128) SB[tid] = g_mbase[(m_base + tid) * KK + tap];
        else           SW[tid - 128] = g_mw[(m_base + tid - 128) * KK + tap];
        const __half* wb = g_wth + (size_t)(tap * CO + n_base) * CI;

        for (int c0 = 0; c0 < CI; c0 += 32) {
            __syncthreads();
            // ---- build A tile: 128 m x 32 c, gather + fp16 hi/lo split ----
            #pragma unroll
            for (int j = 0; j < 4; j++) {
                int task = tid + 256 * j;           // 0..1023
                int q = task & 7;                   // c-quad
                int m = task >> 3;                  // 0..127
                int4 bs = SB[m];
                float4 ws = SW[m];
                int c = c0 + q * 4;
                float4 p0 = *(const float4*)&g_xt[bs.x + c];
                float4 p1 = *(const float4*)&g_xt[bs.y + c];
                float4 p2 = *(const float4*)&g_xt[bs.z + c];
                float4 p3 = *(const float4*)&g_xt[bs.w + c];
                float v0 = ws.x * p0.x + ws.y * p1.x + ws.z * p2.x + ws.w * p3.x;
                float v1 = ws.x * p0.y + ws.y * p1.y + ws.z * p2.y + ws.w * p3.y;
                float v2 = ws.x * p0.z + ws.y * p1.z + ws.z * p2.z + ws.w * p3.z;
                float v3 = ws.x * p0.w + ws.y * p1.w + ws.z * p2.w + ws.w * p3.w;
                __half h0 = __float2half_rn(v0), h1 = __float2half_rn(v1);
                __half h2 = __float2half_rn(v2), h3 = __float2half_rn(v3);
                __half2 hp0; hp0.x = h0; hp0.y = h1;
                __half2 hp1; hp1.x = h2; hp1.y = h3;
                __half2 lp0;
                lp0.x = __float2half_rn(v0 - __half2float(h0));
                lp0.y = __float2half_rn(v1 - __half2float(h1));
                __half2 lp1;
                lp1.x = __float2half_rn(v2 - __half2float(h2));
                lp1.y = __float2half_rn(v3 - __half2float(h3));
                int off = m * PAD + q * 4;
                uint2 ph; ph.x = *(unsigned*)&hp0; ph.y = *(unsigned*)&hp1;
                uint2 pl; pl.x = *(unsigned*)&lp0; pl.y = *(unsigned*)&lp1;
                *(uint2*)&As_hi[off] = ph;
                *(uint2*)&As_lo[off] = pl;
            }
            // ---- load B tile: 128 n x 32 c (fp16 single) ----
            #pragma unroll
            for (int j = 0; j < 2; j++) {
                int idx = tid + 256 * j;            // 0..511
                int n = idx >> 2;
                int part = idx & 3;
                uint4 v = *(const uint4*)&wb[(size_t)n * CI + c0 + part * 8];
                *(uint4*)&Bs[n * PAD + part * 8] = v;
            }
            __syncthreads();
            // ---- mma: 2 k16 steps, 2 passes (hi, lo) ----
            #pragma unroll
            for (int ks = 0; ks < 2; ks++) {
                unsigned ahi[2][4], alo[2][4];
                #pragma unroll
                for (int mf = 0; mf < 2; mf++) {
                    unsigned row = (unsigned)(wm * 32 + mf * 16) + a_row;
                    unsigned boff = row * (PAD * 2) + (ks * 16 + a_koff) * 2;
                    ldmat_x4(ahi[mf], as_hi_base + boff);
                    ldmat_x4(alo[mf], as_lo_base + boff);
                }
                #pragma unroll
                for (int nf = 0; nf < 8; nf++) {
                    int n = wn * 64 + nf * 8 + (lane >> 2);
                    int k0 = ks * 16 + (lane & 3) * 2;
                    unsigned bb[2];
                    bb[0] = *(const unsigned*)&Bs[n * PAD + k0];
                    bb[1] = *(const unsigned*)&Bs[n * PAD + k0 + 8];
                    #pragma unroll
                    for (int mf = 0; mf < 2; mf++) {
                        mma_f16(acc[mf][nf], ahi[mf], bb);
                        mma_f16(acc[mf][nf], alo[mf], bb);
                    }
                }
            }
        }
    }

    // ---- epilogue: BN(+bias) + ReLU, write NCHW ----
    int g = lane >> 2;
    int cq = (lane & 3) * 2;
    #pragma unroll
    for (int mf = 0; mf < 2; mf++) {
        int row0 = m_base + wm * 32 + mf * 16 + g;
        #pragma unroll
        for (int half = 0; half < 2; half++) {
            int m = row0 + half * 8;
            int b = m >> 12, h = (m >> 6) & 63, w = m & 63;
            float* orow = out + ((size_t)b * CO * HN + h) * WN + w;
            #pragma unroll
            for (int nf = 0; nf < 8; nf++) {
                int nl0 = wn * 64 + nf * 8 + cq;
                #pragma unroll
                for (int j = 0; j < 2; j++) {
                    int nl = nl0 + j;
                    int o = n_base + nl;
                    float v = acc[mf][nf][half * 2 + j] * s_scale[nl] + s_shift[nl];
                    orow[(size_t)o * HN * WN] = fmaxf(v, 0.f);
                }
            }
        }
    }
}

// ---------------- launch ----------------
extern "C" void kernel_launch(void* const* d_in, const int* in_sizes, int n_in,
                              void* d_out, int out_size) {
    const float* x      = (const float*)d_in[0];
    const float* w_off  = (const float*)d_in[1];
    const float* b_off  = (const float*)d_in[2];
    const float* weight = (const float*)d_in[3];
    const float* bias   = (const float*)d_in[4];
    const float* gamma  = (const float*)d_in[5];
    const float* beta   = (const float*)d_in[6];
    const float* rmean  = (const float*)d_in[7];
    const float* rvar   = (const float*)d_in[8];
    float* out = (float*)d_out;

    dim3 tgrid(HN * WN / 32, CI / 32, BN_);
    k_transpose_x<<<tgrid, dim3(32, 8)>>>(x);
    k_prep_w<<<256, 256>>>(w_off, weight);
    k_offconv<<<BN_ * HN, 256>>>(b_off);
    k_meta<<<(BN_ * HN * WN * KK + 255) / 256, 256>>>();
    k_main<<<dim3(BN_ * HN * WN / 128, CO / 128), 256>>>(bias, gamma, beta, rmean, rvar, out);
}

// round 5
// speedup vs baseline: 4.4009x; 1.0898x over previous
#include <cuda_runtime.h>
#include <cuda_fp16.h>
#include <math.h>

#define BN_ 4
#define CI 256
#define CO 256
#define HN 64
#define WN 64
#define KK 9
#define EPS 1e-5f
#define PAD 40

// ---------------- scratch (device globals; no allocation) ----------------
__device__ float  g_xt[BN_*HN*WN*CI];       // x transposed to [b][y][x][c]
__device__ __half g_woffh[KK*32*CI];        // offset weights fp16 [tap][o(pad32)][c]
__device__ __half g_wth[KK*CO*CI];          // main weights fp16 [tap][o][c]
__device__ float  g_om[BN_*HN*WN*32];       // offset conv out [m][o(pad32)]
__device__ int4   g_mbase[BN_*HN*WN*KK];    // 4 corner base indices into g_xt
__device__ float4 g_mw[BN_*HN*WN*KK];       // 4 corner weights (mask*valid premult)

static __device__ __forceinline__ unsigned smem_u32(const void* p) {
    return (unsigned)__cvta_generic_to_shared(p);
}

static __device__ __forceinline__ void mma_f16(float* c, const unsigned* a, const unsigned* b) {
    asm volatile(
        "mma.sync.aligned.m16n8k16.row.col.f32.f16.f16.f32 "
        "{%0,%1,%2,%3}, {%4,%5,%6,%7}, {%8,%9}, {%0,%1,%2,%3};"
        : "+f"(c[0]), "+f"(c[1]), "+f"(c[2]), "+f"(c[3])
        : "r"(a[0]), "r"(a[1]), "r"(a[2]), "r"(a[3]), "r"(b[0]), "r"(b[1]));
}

static __device__ __forceinline__ void ldmat_x4(unsigned* r, unsigned addr) {
    asm volatile("ldmatrix.sync.aligned.m8n8.x4.shared.b16 {%0,%1,%2,%3}, [%4];"
                 : "=r"(r[0]), "=r"(r[1]), "=r"(r[2]), "=r"(r[3]) : "r"(addr));
}

// ---------------- T1: NCHW -> NHWC transpose of x ----------------
__global__ void k_transpose_x(const float* __restrict__ x) {
    __shared__ float tile[32][33];
    int b  = blockIdx.z;
    int c0 = blockIdx.y * 32;
    int p0 = blockIdx.x * 32;
    int tx = threadIdx.x, ty = threadIdx.y;
    const float* xb = x + (size_t)b * CI * HN * WN;
    #pragma unroll
    for (int j = 0; j < 32; j += 8)
        tile[ty + j][tx] = xb[(c0 + ty + j) * (HN * WN) + p0 + tx];
    __syncthreads();
    float* xtb = g_xt + (size_t)b * HN * WN * CI;
    #pragma unroll
    for (int j = 0; j < 32; j += 8)
        xtb[(p0 + ty + j) * CI + c0 + tx] = tile[tx][ty + j];
}

// ---------------- T2: weight re-layouts (fp16) ----------------
__global__ void k_prep_w(const float* __restrict__ w_off, const float* __restrict__ weight) {
    int stride = gridDim.x * blockDim.x;
    int tid = blockIdx.x * blockDim.x + threadIdx.x;
    for (int i = tid; i < KK * 32 * CI; i += stride) {
        int c = i & 255; int to = i >> 8; int o = to & 31; int tap = to >> 5;
        float v = (o < 27) ? w_off[(o * CI + c) * KK + tap] : 0.f;
        g_woffh[i] = __float2half_rn(v);
    }
    for (int i = tid; i < KK * CO * CI; i += stride) {
        int c = i & 255; int to = i >> 8; int o = to & 255; int tap = to >> 8;
        g_wth[i] = __float2half_rn(weight[(o * CI + c) * KK + tap]);
    }
}

// ---------------- O: offset conv, fp16 tensor GEMM (BM=64, BN=32, BK=32) ----------------
__global__ __launch_bounds__(256) void k_offconv(const float* __restrict__ b_off) {
    __shared__ __align__(16) __half As[64 * PAD];
    __shared__ __align__(16) __half Bs[32 * PAD];
    int row = blockIdx.x;            // b*64+h
    int b = row >> 6, h = row & 63;
    int tid = threadIdx.x;
    int lane = tid & 31;
    int wid = tid >> 5;
    int wm = wid & 3;
    int wn = wid >> 2;

    float acc[2][4];
    #pragma unroll
    for (int i = 0; i < 2; i++)
        #pragma unroll
        for (int j = 0; j < 4; j++) acc[i][j] = 0.f;

    unsigned a_row = (unsigned)(lane & 15);
    unsigned a_koff = (unsigned)((lane >> 4) * 8);
    unsigned as_base = smem_u32(As);

    for (int tap = 0; tap < KK; tap++) {
        int ky = tap / 3 - 1, kx = tap % 3 - 1;
        int y = h + ky;
        bool yok = (y >= 0 && y < HN);
        const float* xrow = g_xt + ((size_t)(b * HN + (yok ? y : 0)) * WN) * CI;
        for (int c0 = 0; c0 < CI; c0 += 32) {
            __syncthreads();
            #pragma unroll
            for (int j = 0; j < 2; j++) {
                int task = tid + 256 * j;
                int q = task & 7;
                int m = task >> 3;
                int xx = m + kx;
                float4 p = make_float4(0.f, 0.f, 0.f, 0.f);
                if (yok && xx >= 0 && xx < WN)
                    p = *(const float4*)&xrow[xx * CI + c0 + q * 4];
                __half2 h0; h0.x = __float2half_rn(p.x); h0.y = __float2half_rn(p.y);
                __half2 h1; h1.x = __float2half_rn(p.z); h1.y = __float2half_rn(p.w);
                uint2 pk; pk.x = *(unsigned*)&h0; pk.y = *(unsigned*)&h1;
                *(uint2*)&As[m * PAD + q * 4] = pk;
            }
            if (tid < 128) {
                int n = tid >> 2, part = tid & 3;
                uint4 v = *(const uint4*)&g_woffh[((size_t)(tap * 32 + n)) * CI + c0 + part * 8];
                *(uint4*)&Bs[n * PAD + part * 8] = v;
            }
            __syncthreads();
            #pragma unroll
            for (int ks = 0; ks < 2; ks++) {
                unsigned a[4];
                unsigned boff = (wm * 16 + a_row) * (PAD * 2) + (ks * 16 + a_koff) * 2;
                ldmat_x4(a, as_base + boff);
                #pragma unroll
                for (int nf = 0; nf < 2; nf++) {
                    int n = wn * 16 + nf * 8 + (lane >> 2);
                    int k0 = ks * 16 + (lane & 3) * 2;
                    unsigned bb[2];
                    bb[0] = *(const unsigned*)&Bs[n * PAD + k0];
                    bb[1] = *(const unsigned*)&Bs[n * PAD + k0 + 8];
                    mma_f16(acc[nf], a, bb);
                }
            }
        }
    }
    int g = lane >> 2;
    int cq = (lane & 3) * 2;
    #pragma unroll
    for (int nf = 0; nf < 2; nf++) {
        #pragma unroll
        for (int half = 0; half < 2; half++) {
            int m = wm * 16 + half * 8 + g;
            #pragma unroll
            for (int j = 0; j < 2; j++) {
                int n = wn * 16 + nf * 8 + cq + j;
                float bo = (n < 27) ? b_off[n] : 0.f;
                g_om[(row * 64 + m) * 32 + n] = acc[nf][half * 2 + j] + bo;
            }
        }
    }
}

// ---------------- M: sampling metadata ----------------
__global__ void k_meta() {
    int idx = blockIdx.x * blockDim.x + threadIdx.x;
    if (idx >= BN_ * HN * WN * KK) return;
    int k = idx % KK; int m = idx / KK;
    int w = m & 63, h = (m >> 6) & 63, b = m >> 12;
    float dy = g_om[m * 32 + k];
    float dx = g_om[m * 32 + 9 + k];
    float mm = g_om[m * 32 + 18 + k];
    float mask = 1.f / (1.f + expf(-mm));
    float py = (float)h + (float)(k / 3 - 1) + dy;
    float px = (float)w + (float)(k % 3 - 1) + dx;
    float y0f = floorf(py), x0f = floorf(px);
    float ly = py - y0f, lx = px - x0f;
    int y0 = (int)y0f, x0 = (int)x0f;
    int y1 = y0 + 1, x1 = x0 + 1;
    float vy0 = (y0 >= 0 && y0 < HN) ? 1.f : 0.f;
    float vy1 = (y1 >= 0 && y1 < HN) ? 1.f : 0.f;
    float vx0 = (x0 >= 0 && x0 < WN) ? 1.f : 0.f;
    float vx1 = (x1 >= 0 && x1 < WN) ? 1.f : 0.f;
    int yc0 = min(max(y0, 0), HN - 1), yc1 = min(max(y1, 0), HN - 1);
    int xc0 = min(max(x0, 0), WN - 1), xc1 = min(max(x1, 0), WN - 1);
    float4 wv;
    wv.x = (1.f - ly) * (1.f - lx) * mask * vy0 * vx0;
    wv.y = (1.f - ly) * lx         * mask * vy0 * vx1;
    wv.z = ly * (1.f - lx)         * mask * vy1 * vx0;
    wv.w = ly * lx                 * mask * vy1 * vx1;
    int bb = b * HN * WN;
    int4 bv;
    bv.x = (bb + yc0 * WN + xc0) * CI;
    bv.y = (bb + yc0 * WN + xc1) * CI;
    bv.z = (bb + yc1 * WN + xc0) * CI;
    bv.w = (bb + yc1 * WN + xc1) * CI;
    g_mbase[idx] = bv;
    g_mw[idx] = wv;
}

// ---------------- G: fused sample + fp16x2 GEMM, BM=128 BN=256, pipelined ----------------
// 512 threads = 16 warps; warp tile 32x64; double-buffered smem; 1 sync per K-step.
#define AS_ELEMS (128 * PAD)
#define BS_ELEMS (256 * PAD)
#define STEPS 72   // 9 taps * 8 c0-chunks

__global__ __launch_bounds__(512, 1) void k_main(const float* __restrict__ bias,
                                              const float* __restrict__ gamma,
                                              const float* __restrict__ beta,
                                              const float* __restrict__ rmean,
                                              const float* __restrict__ rvar,
                                              float* __restrict__ out) {
    extern __shared__ __align__(16) char dyn[];
    __half* As_hi = (__half*)dyn;                         // [2][AS_ELEMS]
    __half* As_lo = As_hi + 2 * AS_ELEMS;                 // [2][AS_ELEMS]
    __half* Bs    = As_lo + 2 * AS_ELEMS;                 // [2][BS_ELEMS]
    int4*   SB    = (int4*)(Bs + 2 * BS_ELEMS);           // [2][128]
    float4* SW    = (float4*)(SB + 2 * 128);              // [2][128]
    float*  s_scale = (float*)(SW + 2 * 128);             // [256]
    float*  s_shift = s_scale + 256;                      // [256]

    int m_base = blockIdx.x * 128;
    int tid = threadIdx.x;
    int lane = tid & 31;
    int wid = tid >> 5;
    int wm = wid & 3;          // m-warp: 32 rows
    int wn = wid >> 2;         // n-warp 0..3: 64 cols

    if (tid < 256) {
        float inv = gamma[tid] * rsqrtf(rvar[tid] + EPS);
        s_scale[tid] = inv;
        s_shift[tid] = beta[tid] - rmean[tid] * inv + bias[tid] * inv;
    }
    // meta for tap 0 -> parity buffer 0
    if (tid < 128)      SB[tid] = g_mbase[(m_base + tid) * KK + 0];
    else if (tid < 256) SW[tid - 128] = g_mw[(m_base + tid - 128) * KK + 0];
    __syncthreads();

    float acc[2][8][4];
    #pragma unroll
    for (int i = 0; i < 2; i++)
        #pragma unroll
        for (int j = 0; j < 8; j++)
            #pragma unroll
            for (int q = 0; q < 4; q++) acc[i][j][q] = 0.f;

    unsigned a_row = (unsigned)(lane & 15);
    unsigned a_koff = (unsigned)((lane >> 4) * 8);
    unsigned as_hi_base = smem_u32(As_hi);
    unsigned as_lo_base = smem_u32(As_lo);

    // ---- build step 0 into buffer 0 ----
    {
        const int4*   SBt = SB;        // parity 0
        const float4* SWt = SW;
        #pragma unroll
        for (int j = 0; j < 2; j++) {
            int task = tid + 512 * j;
            int q = task & 7;
            int m = task >> 3;
            int4 bs = SBt[m];
            float4 ws = SWt[m];
            int c = q * 4;
            float4 p0 = *(const float4*)&g_xt[bs.x + c];
            float4 p1 = *(const float4*)&g_xt[bs.y + c];
            float4 p2 = *(const float4*)&g_xt[bs.z + c];
            float4 p3 = *(const float4*)&g_xt[bs.w + c];
            float v0 = ws.x * p0.x + ws.y * p1.x + ws.z * p2.x + ws.w * p3.x;
            float v1 = ws.x * p0.y + ws.y * p1.y + ws.z * p2.y + ws.w * p3.y;
            float v2 = ws.x * p0.z + ws.y * p1.z + ws.z * p2.z + ws.w * p3.z;
            float v3 = ws.x * p0.w + ws.y * p1.w + ws.z * p2.w + ws.w * p3.w;
            __half h0 = __float2half_rn(v0), h1 = __float2half_rn(v1);
            __half h2 = __float2half_rn(v2), h3 = __float2half_rn(v3);
            __half2 hp0; hp0.x = h0; hp0.y = h1;
            __half2 hp1; hp1.x = h2; hp1.y = h3;
            __half2 lp0;
            lp0.x = __float2half_rn(v0 - __half2float(h0));
            lp0.y = __float2half_rn(v1 - __half2float(h1));
            __half2 lp1;
            lp1.x = __float2half_rn(v2 - __half2float(h2));
            lp1.y = __float2half_rn(v3 - __half2float(h3));
            int off = m * PAD + q * 4;
            uint2 ph; ph.x = *(unsigned*)&hp0; ph.y = *(unsigned*)&hp1;
            uint2 pl; pl.x = *(unsigned*)&lp0; pl.y = *(unsigned*)&lp1;
            *(uint2*)&As_hi[off] = ph;
            *(uint2*)&As_lo[off] = pl;
        }
        #pragma unroll
        for (int j = 0; j < 2; j++) {
            int idx = tid + 512 * j;   // 0..1023
            int n = idx >> 2;
            int part = idx & 3;
            uint4 v = *(const uint4*)&g_wth[(size_t)n * CI + part * 8];
            *(uint4*)&Bs[n * PAD + part * 8] = v;
        }
    }
    __syncthreads();

    for (int s = 0; s < STEPS; s++) {
        int cur = s & 1, nxt = cur ^ 1;
        int tap = s >> 3;

        // prefetch next tap's metadata (parity-buffered)
        if ((s & 7) == 0 && tap + 1 < KK) {
            int p = (tap + 1) & 1;
            if (tid < 128)      SB[p * 128 + tid] = g_mbase[(m_base + tid) * KK + tap + 1];
            else if (tid < 256) SW[p * 128 + tid - 128] = g_mw[(m_base + tid - 128) * KK + tap + 1];
        }

        // build step s+1 into buffers [nxt]
        if (s + 1 < STEPS) {
            int s1 = s + 1;
            int tap1 = s1 >> 3;
            int c01 = (s1 & 7) * 32;
            const int4*   SBt = SB + (tap1 & 1) * 128;
            const float4* SWt = SW + (tap1 & 1) * 128;
            __half* ah = As_hi + nxt * AS_ELEMS;
            __half* al = As_lo + nxt * AS_ELEMS;
            #pragma unroll
            for (int j = 0; j < 2; j++) {
                int task = tid + 512 * j;
                int q = task & 7;
                int m = task >> 3;
                int4 bs = SBt[m];
                float4 ws = SWt[m];
                int c = c01 + q * 4;
                float4 p0 = *(const float4*)&g_xt[bs.x + c];
                float4 p1 = *(const float4*)&g_xt[bs.y + c];
                float4 p2 = *(const float4*)&g_xt[bs.z + c];
                float4 p3 = *(const float4*)&g_xt[bs.w + c];
                float v0 = ws.x * p0.x + ws.y * p1.x + ws.z * p2.x + ws.w * p3.x;
                float v1 = ws.x * p0.y + ws.y * p1.y + ws.z * p2.y + ws.w * p3.y;
                float v2 = ws.x * p0.z + ws.y * p1.z + ws.z * p2.z + ws.w * p3.z;
                float v3 = ws.x * p0.w + ws.y * p1.w + ws.z * p2.w + ws.w * p3.w;
                __half h0 = __float2half_rn(v0), h1 = __float2half_rn(v1);
                __half h2 = __float2half_rn(v2), h3 = __float2half_rn(v3);
                __half2 hp0; hp0.x = h0; hp0.y = h1;
                __half2 hp1; hp1.x = h2; hp1.y = h3;
                __half2 lp0;
                lp0.x = __float2half_rn(v0 - __half2float(h0));
                lp0.y = __float2half_rn(v1 - __half2float(h1));
                __half2 lp1;
                lp1.x = __float2half_rn(v2 - __half2float(h2));
                lp1.y = __float2half_rn(v3 - __half2float(h3));
                int off = m * PAD + q * 4;
                uint2 ph; ph.x = *(unsigned*)&hp0; ph.y = *(unsigned*)&hp1;
                uint2 pl; pl.x = *(unsigned*)&lp0; pl.y = *(unsigned*)&lp1;
                *(uint2*)&ah[off] = ph;
                *(uint2*)&al[off] = pl;
            }
            const __half* wb = g_wth + (size_t)tap1 * CO * CI + c01;
            __half* bsm = Bs + nxt * BS_ELEMS;
            #pragma unroll
            for (int j = 0; j < 2; j++) {
                int idx = tid + 512 * j;
                int n = idx >> 2;
                int part = idx & 3;
                uint4 v = *(const uint4*)&wb[(size_t)n * CI + part * 8];
                *(uint4*)&bsm[n * PAD + part * 8] = v;
            }
        }

        // mma on buffers [cur]
        {
            unsigned ah_base = as_hi_base + cur * (AS_ELEMS * 2);
            unsigned al_base = as_lo_base + cur * (AS_ELEMS * 2);
            const __half* bsm = Bs + cur * BS_ELEMS;
            #pragma unroll
            for (int ks = 0; ks < 2; ks++) {
                unsigned ahi[2][4], alo[2][4];
                #pragma unroll
                for (int mf = 0; mf < 2; mf++) {
                    unsigned row = (unsigned)(wm * 32 + mf * 16) + a_row;
                    unsigned boff = row * (PAD * 2) + (ks * 16 + a_koff) * 2;
                    ldmat_x4(ahi[mf], ah_base + boff);
                    ldmat_x4(alo[mf], al_base + boff);
                }
                #pragma unroll
                for (int nf = 0; nf < 8; nf++) {
                    int n = wn * 64 + nf * 8 + (lane >> 2);
                    int k0 = ks * 16 + (lane & 3) * 2;
                    unsigned bb[2];
                    bb[0] = *(const unsigned*)&bsm[n * PAD + k0];
                    bb[1] = *(const unsigned*)&bsm[n * PAD + k0 + 8];
                    #pragma unroll
                    for (int mf = 0; mf < 2; mf++) {
                        mma_f16(acc[mf][nf], ahi[mf], bb);
                        mma_f16(acc[mf][nf], alo[mf], bb);
                    }
                }
            }
        }
        __syncthreads();
    }

    // ---- epilogue: BN(+bias) + ReLU, write NCHW ----
    int g = lane >> 2;
    int cq = (lane & 3) * 2;
    #pragma unroll
    for (int mf = 0; mf < 2; mf++) {
        int row0 = m_base + wm * 32 + mf * 16 + g;
        #pragma unroll
        for (int half = 0; half < 2; half++) {
            int m = row0 + half * 8;
            int b = m >> 12, h = (m >> 6) & 63, w = m & 63;
            float* orow = out + ((size_t)b * CO * HN + h) * WN + w;
            #pragma unroll
            for (int nf = 0; nf < 8; nf++) {
                int nl0 = wn * 64 + nf * 8 + cq;
                #pragma unroll
                for (int j = 0; j < 2; j++) {
                    int nl = nl0 + j;
                    float v = acc[mf][nf][half * 2 + j] * s_scale[nl] + s_shift[nl];
                    orow[(size_t)nl * HN * WN] = fmaxf(v, 0.f);
                }
            }
        }
    }
}

// ---------------- launch ----------------
#define KMAIN_SMEM (2*AS_ELEMS*2*2 + 2*BS_ELEMS*2 + 2*128*16 + 2*128*16 + 2*256*4)

extern "C" void kernel_launch(void* const* d_in, const int* in_sizes, int n_in,
                              void* d_out, int out_size) {
    const float* x      = (const float*)d_in[0];
    const float* w_off  = (const float*)d_in[1];
    const float* b_off  = (const float*)d_in[2];
    const float* weight = (const float*)d_in[3];
    const float* bias   = (const float*)d_in[4];
    const float* gamma  = (const float*)d_in[5];
    const float* beta   = (const float*)d_in[6];
    const float* rmean  = (const float*)d_in[7];
    const float* rvar   = (const float*)d_in[8];
    float* out = (float*)d_out;

    static bool attr_done = false;
    if (!attr_done) {
        cudaFuncSetAttribute(k_main, cudaFuncAttributeMaxDynamicSharedMemorySize, KMAIN_SMEM);
        attr_done = true;
    }

    dim3 tgrid(HN * WN / 32, CI / 32, BN_);
    k_transpose_x<<<tgrid, dim3(32, 8)>>>(x);
    k_prep_w<<<256, 256>>>(w_off, weight);
    k_offconv<<<BN_ * HN, 256>>>(b_off);
    k_meta<<<(BN_ * HN * WN * KK + 255) / 256, 256>>>();
    k_main<<<BN_ * HN * WN / 128, 512, KMAIN_SMEM>>>(bias, gamma, beta, rmean, rvar, out);
}

// round 6
// speedup vs baseline: 5.5542x; 1.2621x over previous
#include <cuda_runtime.h>
#include <cuda_fp16.h>
#include <math.h>

#define BN_ 4
#define CI 256
#define CO 256
#define HN 64
#define WN 64
#define KK 9
#define EPS 1e-5f
#define PAD 40

// ---------------- scratch (device globals; no allocation) ----------------
__device__ float  g_xt[BN_*HN*WN*CI];       // x transposed to [b][y][x][c]
__device__ __half g_woffh[KK*32*CI];        // offset weights fp16 [tap][o(pad32)][c]
__device__ __half g_wth[KK*CO*CI];          // main weights fp16 [tap][o][c]
__device__ int4   g_mbase[BN_*HN*WN*KK];    // 4 corner base indices into g_xt
__device__ float4 g_mw[BN_*HN*WN*KK];       // 4 corner weights (mask*valid premult)

static __device__ __forceinline__ unsigned smem_u32(const void* p) {
    return (unsigned)__cvta_generic_to_shared(p);
}

static __device__ __forceinline__ void mma_f16(float* c, const unsigned* a, const unsigned* b) {
    asm volatile(
        "mma.sync.aligned.m16n8k16.row.col.f32.f16.f16.f32 "
        "{%0,%1,%2,%3}, {%4,%5,%6,%7}, {%8,%9}, {%0,%1,%2,%3};"
        : "+f"(c[0]), "+f"(c[1]), "+f"(c[2]), "+f"(c[3])
        : "r"(a[0]), "r"(a[1]), "r"(a[2]), "r"(a[3]), "r"(b[0]), "r"(b[1]));
}

static __device__ __forceinline__ void ldmat_x4(unsigned* r, unsigned addr) {
    asm volatile("ldmatrix.sync.aligned.m8n8.x4.shared.b16 {%0,%1,%2,%3}, [%4];"
                 : "=r"(r[0]), "=r"(r[1]), "=r"(r[2]), "=r"(r[3]) : "r"(addr));
}

// ---------------- T1: NCHW -> NHWC transpose of x ----------------
__global__ void k_transpose_x(const float* __restrict__ x) {
    __shared__ float tile[32][33];
    int b  = blockIdx.z;
    int c0 = blockIdx.y * 32;
    int p0 = blockIdx.x * 32;
    int tx = threadIdx.x, ty = threadIdx.y;
    const float* xb = x + (size_t)b * CI * HN * WN;
    #pragma unroll
    for (int j = 0; j < 32; j += 8)
        tile[ty + j][tx] = xb[(c0 + ty + j) * (HN * WN) + p0 + tx];
    __syncthreads();
    float* xtb = g_xt + (size_t)b * HN * WN * CI;
    #pragma unroll
    for (int j = 0; j < 32; j += 8)
        xtb[(p0 + ty + j) * CI + c0 + tx] = tile[tx][ty + j];
}

// ---------------- T2: weight re-layouts (fp16) ----------------
__global__ void k_prep_w(const float* __restrict__ w_off, const float* __restrict__ weight) {
    int stride = gridDim.x * blockDim.x;
    int tid = blockIdx.x * blockDim.x + threadIdx.x;
    for (int i = tid; i < KK * 32 * CI; i += stride) {
        int c = i & 255; int to = i >> 8; int o = to & 31; int tap = to >> 5;
        float v = (o < 27) ? w_off[(o * CI + c) * KK + tap] : 0.f;
        g_woffh[i] = __float2half_rn(v);
    }
    for (int i = tid; i < KK * CO * CI; i += stride) {
        int c = i & 255; int to = i >> 8; int o = to & 255; int tap = to >> 8;
        g_wth[i] = __float2half_rn(weight[(o * CI + c) * KK + tap]);
    }
}

// ---------------- O: offset conv (tensor GEMM) + fused sampling metadata ----------------
__global__ __launch_bounds__(256) void k_offconv(const float* __restrict__ b_off) {
    __shared__ __align__(16) __half As[64 * PAD];
    __shared__ __align__(16) __half Bs[32 * PAD];
    __shared__ float som[64][32];
    int row = blockIdx.x;            // b*64+h
    int b = row >> 6, h = row & 63;
    int tid = threadIdx.x;
    int lane = tid & 31;
    int wid = tid >> 5;
    int wm = wid & 3;
    int wn = wid >> 2;

    float acc[2][4];
    #pragma unroll
    for (int i = 0; i < 2; i++)
        #pragma unroll
        for (int j = 0; j < 4; j++) acc[i][j] = 0.f;

    unsigned a_row = (unsigned)(lane & 15);
    unsigned a_koff = (unsigned)((lane >> 4) * 8);
    unsigned as_base = smem_u32(As);

    for (int tap = 0; tap < KK; tap++) {
        int ky = tap / 3 - 1, kx = tap % 3 - 1;
        int y = h + ky;
        bool yok = (y >= 0 && y < HN);
        const float* xrow = g_xt + ((size_t)(b * HN + (yok ? y : 0)) * WN) * CI;
        for (int c0 = 0; c0 < CI; c0 += 32) {
            __syncthreads();
            #pragma unroll
            for (int j = 0; j < 2; j++) {
                int task = tid + 256 * j;
                int q = task & 7;
                int m = task >> 3;
                int xx = m + kx;
                float4 p = make_float4(0.f, 0.f, 0.f, 0.f);
                if (yok && xx >= 0 && xx < WN)
                    p = *(const float4*)&xrow[xx * CI + c0 + q * 4];
                __half2 h0; h0.x = __float2half_rn(p.x); h0.y = __float2half_rn(p.y);
                __half2 h1; h1.x = __float2half_rn(p.z); h1.y = __float2half_rn(p.w);
                uint2 pk; pk.x = *(unsigned*)&h0; pk.y = *(unsigned*)&h1;
                *(uint2*)&As[m * PAD + q * 4] = pk;
            }
            if (tid < 128) {
                int n = tid >> 2, part = tid & 3;
                uint4 v = *(const uint4*)&g_woffh[((size_t)(tap * 32 + n)) * CI + c0 + part * 8];
                *(uint4*)&Bs[n * PAD + part * 8] = v;
            }
            __syncthreads();
            #pragma unroll
            for (int ks = 0; ks < 2; ks++) {
                unsigned a[4];
                unsigned boff = (wm * 16 + a_row) * (PAD * 2) + (ks * 16 + a_koff) * 2;
                ldmat_x4(a, as_base + boff);
                #pragma unroll
                for (int nf = 0; nf < 2; nf++) {
                    int n = wn * 16 + nf * 8 + (lane >> 2);
                    int k0 = ks * 16 + (lane & 3) * 2;
                    unsigned bb[2];
                    bb[0] = *(const unsigned*)&Bs[n * PAD + k0];
                    bb[1] = *(const unsigned*)&Bs[n * PAD + k0 + 8];
                    mma_f16(acc[nf], a, bb);
                }
            }
        }
    }
    // stage offset-conv outputs in smem
    {
        int g = lane >> 2;
        int cq = (lane & 3) * 2;
        #pragma unroll
        for (int nf = 0; nf < 2; nf++) {
            #pragma unroll
            for (int half = 0; half < 2; half++) {
                int m = wm * 16 + half * 8 + g;
                #pragma unroll
                for (int j = 0; j < 2; j++) {
                    int n = wn * 16 + nf * 8 + cq + j;
                    som[m][n] = acc[nf][half * 2 + j];
                }
            }
        }
    }
    __syncthreads();
    // fused meta: 64 m-positions x 9 taps = 576 tasks
    for (int idx = tid; idx < 64 * KK; idx += 256) {
        int k = idx % KK; int w = idx / KK;
        float dy = som[w][k]      + b_off[k];
        float dx = som[w][9 + k]  + b_off[9 + k];
        float mm = som[w][18 + k] + b_off[18 + k];
        float mask = 1.f / (1.f + expf(-mm));
        float py = (float)h + (float)(k / 3 - 1) + dy;
        float px = (float)w + (float)(k % 3 - 1) + dx;
        float y0f = floorf(py), x0f = floorf(px);
        float ly = py - y0f, lx = px - x0f;
        int y0 = (int)y0f, x0 = (int)x0f;
        int y1 = y0 + 1, x1 = x0 + 1;
        float vy0 = (y0 >= 0 && y0 < HN) ? 1.f : 0.f;
        float vy1 = (y1 >= 0 && y1 < HN) ? 1.f : 0.f;
        float vx0 = (x0 >= 0 && x0 < WN) ? 1.f : 0.f;
        float vx1 = (x1 >= 0 && x1 < WN) ? 1.f : 0.f;
        int yc0 = min(max(y0, 0), HN - 1), yc1 = min(max(y1, 0), HN - 1);
        int xc0 = min(max(x0, 0), WN - 1), xc1 = min(max(x1, 0), WN - 1);
        float4 wv;
        wv.x = (1.f - ly) * (1.f - lx) * mask * vy0 * vx0;
        wv.y = (1.f - ly) * lx         * mask * vy0 * vx1;
        wv.z = ly * (1.f - lx)         * mask * vy1 * vx0;
        wv.w = ly * lx                 * mask * vy1 * vx1;
        int bb = b * HN * WN;
        int4 bv;
        bv.x = (bb + yc0 * WN + xc0) * CI;
        bv.y = (bb + yc0 * WN + xc1) * CI;
        bv.z = (bb + yc1 * WN + xc0) * CI;
        bv.w = (bb + yc1 * WN + xc1) * CI;
        int gidx = (row * 64 + w) * KK + k;
        g_mbase[gidx] = bv;
        g_mw[gidx] = wv;
    }
}

// ---------------- G: fused sample + single-fp16 GEMM, BM=128 BN=256, pipelined ----------------
// 512 threads = 16 warps; warp tile 32x64; double-buffered smem; 1 sync per K-step.
#define AS_ELEMS (128 * PAD)
#define BS_ELEMS (256 * PAD)
#define STEPS 72   // 9 taps * 8 c0-chunks

__global__ __launch_bounds__(512, 1) void k_main(const float* __restrict__ bias,
                                              const float* __restrict__ gamma,
                                              const float* __restrict__ beta,
                                              const float* __restrict__ rmean,
                                              const float* __restrict__ rvar,
                                              float* __restrict__ out) {
    extern __shared__ __align__(16) char dyn[];
    __half* As    = (__half*)dyn;                         // [2][AS_ELEMS]
    __half* Bs    = As + 2 * AS_ELEMS;                    // [2][BS_ELEMS]
    int4*   SB    = (int4*)(Bs + 2 * BS_ELEMS);           // [2][128]
    float4* SW    = (float4*)(SB + 2 * 128);              // [2][128]
    float*  s_scale = (float*)(SW + 2 * 128);             // [256]
    float*  s_shift = s_scale + 256;                      // [256]

    int m_base = blockIdx.x * 128;
    int tid = threadIdx.x;
    int lane = tid & 31;
    int wid = tid >> 5;
    int wm = wid & 3;          // m-warp: 32 rows
    int wn = wid >> 2;         // n-warp 0..3: 64 cols

    if (tid < 256) {
        float inv = gamma[tid] * rsqrtf(rvar[tid] + EPS);
        s_scale[tid] = inv;
        s_shift[tid] = beta[tid] - rmean[tid] * inv + bias[tid] * inv;
    }
    if (tid < 128)      SB[tid] = g_mbase[(m_base + tid) * KK + 0];
    else if (tid < 256) SW[tid - 128] = g_mw[(m_base + tid - 128) * KK + 0];
    __syncthreads();

    float acc[2][8][4];
    #pragma unroll
    for (int i = 0; i < 2; i++)
        #pragma unroll
        for (int j = 0; j < 8; j++)
            #pragma unroll
            for (int q = 0; q < 4; q++) acc[i][j][q] = 0.f;

    unsigned a_row = (unsigned)(lane & 15);
    unsigned a_koff = (unsigned)((lane >> 4) * 8);
    unsigned as_base = smem_u32(As);

    // ---- build step 0 into buffer 0 ----
    {
        #pragma unroll
        for (int j = 0; j < 2; j++) {
            int task = tid + 512 * j;
            int q = task & 7;
            int m = task >> 3;
            int4 bs = SB[m];
            float4 ws = SW[m];
            int c = q * 4;
            float4 p0 = *(const float4*)&g_xt[bs.x + c];
            float4 p1 = *(const float4*)&g_xt[bs.y + c];
            float4 p2 = *(const float4*)&g_xt[bs.z + c];
            float4 p3 = *(const float4*)&g_xt[bs.w + c];
            float v0 = ws.x * p0.x + ws.y * p1.x + ws.z * p2.x + ws.w * p3.x;
            float v1 = ws.x * p0.y + ws.y * p1.y + ws.z * p2.y + ws.w * p3.y;
            float v2 = ws.x * p0.z + ws.y * p1.z + ws.z * p2.z + ws.w * p3.z;
            float v3 = ws.x * p0.w + ws.y * p1.w + ws.z * p2.w + ws.w * p3.w;
            __half2 hp0; hp0.x = __float2half_rn(v0); hp0.y = __float2half_rn(v1);
            __half2 hp1; hp1.x = __float2half_rn(v2); hp1.y = __float2half_rn(v3);
            uint2 ph; ph.x = *(unsigned*)&hp0; ph.y = *(unsigned*)&hp1;
            *(uint2*)&As[m * PAD + q * 4] = ph;
        }
        #pragma unroll
        for (int j = 0; j < 2; j++) {
            int idx = tid + 512 * j;   // 0..1023
            int n = idx >> 2;
            int part = idx & 3;
            uint4 v = *(const uint4*)&g_wth[(size_t)n * CI + part * 8];
            *(uint4*)&Bs[n * PAD + part * 8] = v;
        }
    }
    __syncthreads();

    for (int s = 0; s < STEPS; s++) {
        int cur = s & 1, nxt = cur ^ 1;
        int tap = s >> 3;

        // prefetch next tap's metadata (parity-buffered)
        if ((s & 7) == 0 && tap + 1 < KK) {
            int p = (tap + 1) & 1;
            if (tid < 128)      SB[p * 128 + tid] = g_mbase[(m_base + tid) * KK + tap + 1];
            else if (tid < 256) SW[p * 128 + tid - 128] = g_mw[(m_base + tid - 128) * KK + tap + 1];
        }

        // build step s+1 into buffers [nxt]
        if (s + 1 < STEPS) {
            int s1 = s + 1;
            int tap1 = s1 >> 3;
            int c01 = (s1 & 7) * 32;
            const int4*   SBt = SB + (tap1 & 1) * 128;
            const float4* SWt = SW + (tap1 & 1) * 128;
            __half* ah = As + nxt * AS_ELEMS;
            #pragma unroll
            for (int j = 0; j < 2; j++) {
                int task = tid + 512 * j;
                int q = task & 7;
                int m = task >> 3;
                int4 bs = SBt[m];
                float4 ws = SWt[m];
                int c = c01 + q * 4;
                float4 p0 = *(const float4*)&g_xt[bs.x + c];
                float4 p1 = *(const float4*)&g_xt[bs.y + c];
                float4 p2 = *(const float4*)&g_xt[bs.z + c];
                float4 p3 = *(const float4*)&g_xt[bs.w + c];
                float v0 = ws.x * p0.x + ws.y * p1.x + ws.z * p2.x + ws.w * p3.x;
                float v1 = ws.x * p0.y + ws.y * p1.y + ws.z * p2.y + ws.w * p3.y;
                float v2 = ws.x * p0.z + ws.y * p1.z + ws.z * p2.z + ws.w * p3.z;
                float v3 = ws.x * p0.w + ws.y * p1.w + ws.z * p2.w + ws.w * p3.w;
                __half2 hp0; hp0.x = __float2half_rn(v0); hp0.y = __float2half_rn(v1);
                __half2 hp1; hp1.x = __float2half_rn(v2); hp1.y = __float2half_rn(v3);
                uint2 ph; ph.x = *(unsigned*)&hp0; ph.y = *(unsigned*)&hp1;
                *(uint2*)&ah[m * PAD + q * 4] = ph;
            }
            const __half* wb = g_wth + (size_t)tap1 * CO * CI + c01;
            __half* bsm = Bs + nxt * BS_ELEMS;
            #pragma unroll
            for (int j = 0; j < 2; j++) {
                int idx = tid + 512 * j;
                int n = idx >> 2;
                int part = idx & 3;
                uint4 v = *(const uint4*)&wb[(size_t)n * CI + part * 8];
                *(uint4*)&bsm[n * PAD + part * 8] = v;
            }
        }

        // mma on buffers [cur]
        {
            unsigned ab = as_base + cur * (AS_ELEMS * 2);
            const __half* bsm = Bs + cur * BS_ELEMS;
            #pragma unroll
            for (int ks = 0; ks < 2; ks++) {
                unsigned a[2][4];
                #pragma unroll
                for (int mf = 0; mf < 2; mf++) {
                    unsigned row = (unsigned)(wm * 32 + mf * 16) + a_row;
                    unsigned boff = row * (PAD * 2) + (ks * 16 + a_koff) * 2;
                    ldmat_x4(a[mf], ab + boff);
                }
                #pragma unroll
                for (int nf = 0; nf < 8; nf++) {
                    int n = wn * 64 + nf * 8 + (lane >> 2);
                    int k0 = ks * 16 + (lane & 3) * 2;
                    unsigned bb[2];
                    bb[0] = *(const unsigned*)&bsm[n * PAD + k0];
                    bb[1] = *(const unsigned*)&bsm[n * PAD + k0 + 8];
                    #pragma unroll
                    for (int mf = 0; mf < 2; mf++)
                        mma_f16(acc[mf][nf], a[mf], bb);
                }
            }
        }
        __syncthreads();
    }

    // ---- epilogue: BN(+bias) + ReLU, write NCHW ----
    int g = lane >> 2;
    int cq = (lane & 3) * 2;
    #pragma unroll
    for (int mf = 0; mf < 2; mf++) {
        int row0 = m_base + wm * 32 + mf * 16 + g;
        #pragma unroll
        for (int half = 0; half < 2; half++) {
            int m = row0 + half * 8;
            int b = m >> 12, h = (m >> 6) & 63, w = m & 63;
            float* orow = out + ((size_t)b * CO * HN + h) * WN + w;
            #pragma unroll
            for (int nf = 0; nf < 8; nf++) {
                int nl0 = wn * 64 + nf * 8 + cq;
                #pragma unroll
                for (int j = 0; j < 2; j++) {
                    int nl = nl0 + j;
                    float v = acc[mf][nf][half * 2 + j] * s_scale[nl] + s_shift[nl];
                    orow[(size_t)nl * HN * WN] = fmaxf(v, 0.f);
                }
            }
        }
    }
}

// ---------------- launch ----------------
#define KMAIN_SMEM (2*AS_ELEMS*2 + 2*BS_ELEMS*2 + 2*128*16 + 2*128*16 + 2*256*4)

extern "C" void kernel_launch(void* const* d_in, const int* in_sizes, int n_in,
                              void* d_out, int out_size) {
    const float* x      = (const float*)d_in[0];
    const float* w_off  = (const float*)d_in[1];
    const float* b_off  = (const float*)d_in[2];
    const float* weight = (const float*)d_in[3];
    const float* bias   = (const float*)d_in[4];
    const float* gamma  = (const float*)d_in[5];
    const float* beta   = (const float*)d_in[6];
    const float* rmean  = (const float*)d_in[7];
    const float* rvar   = (const float*)d_in[8];
    float* out = (float*)d_out;

    static bool attr_done = false;
    if (!attr_done) {
        cudaFuncSetAttribute(k_main, cudaFuncAttributeMaxDynamicSharedMemorySize, KMAIN_SMEM);
        attr_done = true;
    }

    dim3 tgrid(HN * WN / 32, CI / 32, BN_);
    k_transpose_x<<<tgrid, dim3(32, 8)>>>(x);
    k_prep_w<<<256, 256>>>(w_off, weight);
    k_offconv<<<BN_ * HN, 256>>>(b_off);
    k_main<<<BN_ * HN * WN / 128, 512, KMAIN_SMEM>>>(bias, gamma, beta, rmean, rvar, out);
}

// round 8
// speedup vs baseline: 6.1627x; 1.1096x over previous
#include <cuda_runtime.h>
#include <cuda_fp16.h>
#include <math.h>

#define BN_ 4
#define CI 256
#define CO 256
#define HN 64
#define WN 64
#define KK 9
#define EPS 1e-5f
#define PAD 40

// ---------------- scratch (device globals; no allocation) ----------------
__device__ __half g_xt[BN_*HN*WN*CI];       // x transposed to [b][y][x][c], fp16
__device__ __half g_woffh[KK*32*CI];        // offset weights fp16 [tap][o(pad32)][c]
__device__ __half g_wth[KK*CO*CI];          // main weights fp16 [tap][o][c]
__device__ int4   g_mbase[BN_*HN*WN*KK];    // 4 corner base indices into g_xt
__device__ float4 g_mw[BN_*HN*WN*KK];       // 4 corner weights (mask*valid premult)

static __device__ __forceinline__ unsigned smem_u32(const void* p) {
    return (unsigned)__cvta_generic_to_shared(p);
}

static __device__ __forceinline__ void mma_f16(float* c, const unsigned* a, const unsigned* b) {
    asm volatile(
        "mma.sync.aligned.m16n8k16.row.col.f32.f16.f16.f32 "
        "{%0,%1,%2,%3}, {%4,%5,%6,%7}, {%8,%9}, {%0,%1,%2,%3};"
        : "+f"(c[0]), "+f"(c[1]), "+f"(c[2]), "+f"(c[3])
        : "r"(a[0]), "r"(a[1]), "r"(a[2]), "r"(a[3]), "r"(b[0]), "r"(b[1]));
}

static __device__ __forceinline__ void ldmat_x4(unsigned* r, unsigned addr) {
    asm volatile("ldmatrix.sync.aligned.m8n8.x4.shared.b16 {%0,%1,%2,%3}, [%4];"
                 : "=r"(r[0]), "=r"(r[1]), "=r"(r[2]), "=r"(r[3]) : "r"(addr));
}

static __device__ __forceinline__ float2 h2f2(unsigned u) {
    return __half22float2(*reinterpret_cast<const __half2*>(&u));
}

// ---------------- T1: NCHW fp32 -> NHWC fp16 transpose of x ----------------
__global__ void k_transpose_x(const float* __restrict__ x) {
    __shared__ float tile[32][33];
    int b  = blockIdx.z;
    int c0 = blockIdx.y * 32;
    int p0 = blockIdx.x * 32;
    int tx = threadIdx.x, ty = threadIdx.y;
    const float* xb = x + (size_t)b * CI * HN * WN;
    #pragma unroll
    for (int j = 0; j < 32; j += 8)
        tile[ty + j][tx] = xb[(c0 + ty + j) * (HN * WN) + p0 + tx];
    __syncthreads();
    __half* xtb = g_xt + (size_t)b * HN * WN * CI;
    #pragma unroll
    for (int j = 0; j < 32; j += 8)
        xtb[(p0 + ty + j) * CI + c0 + tx] = __float2half_rn(tile[tx][ty + j]);
}

// ---------------- T2: weight re-layouts (fp16) ----------------
__global__ void k_prep_w(const float* __restrict__ w_off, const float* __restrict__ weight) {
    int stride = gridDim.x * blockDim.x;
    int tid = blockIdx.x * blockDim.x + threadIdx.x;
    for (int i = tid; i < KK * 32 * CI; i += stride) {
        int c = i & 255; int to = i >> 8; int o = to & 31; int tap = to >> 5;
        float v = (o < 27) ? w_off[(o * CI + c) * KK + tap] : 0.f;
        g_woffh[i] = __float2half_rn(v);
    }
    for (int i = tid; i < KK * CO * CI; i += stride) {
        int c = i & 255; int to = i >> 8; int o = to & 255; int tap = to >> 8;
        g_wth[i] = __float2half_rn(weight[(o * CI + c) * KK + tap]);
    }
}

// ---------------- O: offset conv (tensor GEMM) + fused sampling metadata ----------------
__global__ __launch_bounds__(256) void k_offconv(const float* __restrict__ b_off) {
    __shared__ __align__(16) __half As[64 * PAD];
    __shared__ __align__(16) __half Bs[32 * PAD];
    __shared__ float som[64][32];
    int row = blockIdx.x;            // b*64+h
    int b = row >> 6, h = row & 63;
    int tid = threadIdx.x;
    int lane = tid & 31;
    int wid = tid >> 5;
    int wm = wid & 3;
    int wn = wid >> 2;

    float acc[2][4];
    #pragma unroll
    for (int i = 0; i < 2; i++)
        #pragma unroll
        for (int j = 0; j < 4; j++) acc[i][j] = 0.f;

    unsigned a_row = (unsigned)(lane & 15);
    unsigned a_koff = (unsigned)((lane >> 4) * 8);
    unsigned as_base = smem_u32(As);
    unsigned bs_base = smem_u32(Bs);
    // ldmatrix B lane offset: t=lane>>3 -> (oct=t>>1, khalf=t&1), r=lane&7
    unsigned b_lane_off;
    {
        int t = lane >> 3, r = lane & 7;
        b_lane_off = (unsigned)(((t >> 1) * 8 + r) * (PAD * 2) + (t & 1) * 16);
    }

    for (int tap = 0; tap < KK; tap++) {
        int ky = tap / 3 - 1, kx = tap % 3 - 1;
        int y = h + ky;
        bool yok = (y >= 0 && y < HN);
        const __half* xrow = g_xt + ((size_t)(b * HN + (yok ? y : 0)) * WN) * CI;
        for (int c0 = 0; c0 < CI; c0 += 32) {
            __syncthreads();
            #pragma unroll
            for (int j = 0; j < 2; j++) {
                int task = tid + 256 * j;
                int q = task & 7;
                int m = task >> 3;
                int xx = m + kx;
                uint2 p = make_uint2(0u, 0u);
                if (yok && xx >= 0 && xx < WN)
                    p = *(const uint2*)&xrow[xx * CI + c0 + q * 4];
                *(uint2*)&As[m * PAD + q * 4] = p;
            }
            if (tid < 128) {
                int n = tid >> 2, part = tid & 3;
                uint4 v = *(const uint4*)&g_woffh[((size_t)(tap * 32 + n)) * CI + c0 + part * 8];
                *(uint4*)&Bs[n * PAD + part * 8] = v;
            }
            __syncthreads();
            #pragma unroll
            for (int ks = 0; ks < 2; ks++) {
                unsigned a[4];
                unsigned boff = (wm * 16 + a_row) * (PAD * 2) + (ks * 16 + a_koff) * 2;
                ldmat_x4(a, as_base + boff);
                unsigned bb4[4];
                ldmat_x4(bb4, bs_base + (unsigned)(wn * 16) * (PAD * 2) + (unsigned)(ks * 32) + b_lane_off);
                mma_f16(acc[0], a, bb4);
                mma_f16(acc[1], a, bb4 + 2);
            }
        }
    }
    // stage offset-conv outputs in smem
    {
        int g = lane >> 2;
        int cq = (lane & 3) * 2;
        #pragma unroll
        for (int nf = 0; nf < 2; nf++) {
            #pragma unroll
            for (int half = 0; half < 2; half++) {
                int m = wm * 16 + half * 8 + g;
                #pragma unroll
                for (int j = 0; j < 2; j++) {
                    int n = wn * 16 + nf * 8 + cq + j;
                    som[m][n] = acc[nf][half * 2 + j];
                }
            }
        }
    }
    __syncthreads();
    // fused meta: 64 m-positions x 9 taps = 576 tasks
    for (int idx = tid; idx < 64 * KK; idx += 256) {
        int k = idx % KK; int w = idx / KK;
        float dy = som[w][k]      + b_off[k];
        float dx = som[w][9 + k]  + b_off[9 + k];
        float mm = som[w][18 + k] + b_off[18 + k];
        float mask = 1.f / (1.f + expf(-mm));
        float py = (float)h + (float)(k / 3 - 1) + dy;
        float px = (float)w + (float)(k % 3 - 1) + dx;
        float y0f = floorf(py), x0f = floorf(px);
        float ly = py - y0f, lx = px - x0f;
        int y0 = (int)y0f, x0 = (int)x0f;
        int y1 = y0 + 1, x1 = x0 + 1;
        float vy0 = (y0 >= 0 && y0 < HN) ? 1.f : 0.f;
        float vy1 = (y1 >= 0 && y1 < HN) ? 1.f : 0.f;
        float vx0 = (x0 >= 0 && x0 < WN) ? 1.f : 0.f;
        float vx1 = (x1 >= 0 && x1 < WN) ? 1.f : 0.f;
        int yc0 = min(max(y0, 0), HN - 1), yc1 = min(max(y1, 0), HN - 1);
        int xc0 = min(max(x0, 0), WN - 1), xc1 = min(max(x1, 0), WN - 1);
        float4 wv;
        wv.x = (1.f - ly) * (1.f - lx) * mask * vy0 * vx0;
        wv.y = (1.f - ly) * lx         * mask * vy0 * vx1;
        wv.z = ly * (1.f - lx)         * mask * vy1 * vx0;
        wv.w = ly * lx                 * mask * vy1 * vx1;
        int bb = b * HN * WN;
        int4 bv;
        bv.x = (bb + yc0 * WN + xc0) * CI;
        bv.y = (bb + yc0 * WN + xc1) * CI;
        bv.z = (bb + yc1 * WN + xc0) * CI;
        bv.w = (bb + yc1 * WN + xc1) * CI;
        int gidx = (row * 64 + w) * KK + k;
        g_mbase[gidx] = bv;
        g_mw[gidx] = wv;
    }
}

// ---------------- G: fused sample + fp16 GEMM, BM=128 BN=256, pipelined ----------------
#define AS_ELEMS (128 * PAD)
#define BS_ELEMS (256 * PAD)
#define STEPS 72   // 9 taps * 8 c0-chunks

__global__ __launch_bounds__(512, 1) void k_main(const float* __restrict__ bias,
                                              const float* __restrict__ gamma,
                                              const float* __restrict__ beta,
                                              const float* __restrict__ rmean,
                                              const float* __restrict__ rvar,
                                              float* __restrict__ out) {
    extern __shared__ __align__(16) char dyn[];
    __half* As    = (__half*)dyn;                         // [2][AS_ELEMS]
    __half* Bs    = As + 2 * AS_ELEMS;                    // [2][BS_ELEMS]
    int4*   SB    = (int4*)(Bs + 2 * BS_ELEMS);           // [2][128]
    float4* SW    = (float4*)(SB + 2 * 128);              // [2][128]
    float*  s_scale = (float*)(SW + 2 * 128);             // [256]
    float*  s_shift = s_scale + 256;                      // [256]

    int m_base = blockIdx.x * 128;
    int tid = threadIdx.x;
    int lane = tid & 31;
    int wid = tid >> 5;
    int wm = wid & 3;          // m-warp: 32 rows
    int wn = wid >> 2;         // n-warp 0..3: 64 cols

    if (tid < 256) {
        float inv = gamma[tid] * rsqrtf(rvar[tid] + EPS);
        s_scale[tid] = inv;
        s_shift[tid] = beta[tid] - rmean[tid] * inv + bias[tid] * inv;
    }
    if (tid < 128)      SB[tid] = g_mbase[(m_base + tid) * KK + 0];
    else if (tid < 256) SW[tid - 128] = g_mw[(m_base + tid - 128) * KK + 0];
    __syncthreads();

    float acc[2][8][4];
    #pragma unroll
    for (int i = 0; i < 2; i++)
        #pragma unroll
        for (int j = 0; j < 8; j++)
            #pragma unroll
            for (int q = 0; q < 4; q++) acc[i][j][q] = 0.f;

    unsigned a_row = (unsigned)(lane & 15);
    unsigned a_koff = (unsigned)((lane >> 4) * 8);
    unsigned as_base = smem_u32(As);
    unsigned bs_base = smem_u32(Bs);
    unsigned b_lane_off;
    {
        int t = lane >> 3, r = lane & 7;
        b_lane_off = (unsigned)(((t >> 1) * 8 + r) * (PAD * 2) + (t & 1) * 16);
    }

    // ---- build step 0 into buffer 0 ----
    {
        #pragma unroll
        for (int j = 0; j < 2; j++) {
            int task = tid + 512 * j;
            int q = task & 7;
            int m = task >> 3;
            int4 bs = SB[m];
            float4 ws = SW[m];
            int c = q * 4;
            uint2 r0 = *(const uint2*)&g_xt[bs.x + c];
            uint2 r1 = *(const uint2*)&g_xt[bs.y + c];
            uint2 r2 = *(const uint2*)&g_xt[bs.z + c];
            uint2 r3 = *(const uint2*)&g_xt[bs.w + c];
            float2 f0l = h2f2(r0.x), f0h = h2f2(r0.y);
            float2 f1l = h2f2(r1.x), f1h = h2f2(r1.y);
            float2 f2l = h2f2(r2.x), f2h = h2f2(r2.y);
            float2 f3l = h2f2(r3.x), f3h = h2f2(r3.y);
            float v0 = ws.x * f0l.x + ws.y * f1l.x + ws.z * f2l.x + ws.w * f3l.x;
            float v1 = ws.x * f0l.y + ws.y * f1l.y + ws.z * f2l.y + ws.w * f3l.y;
            float v2 = ws.x * f0h.x + ws.y * f1h.x + ws.z * f2h.x + ws.w * f3h.x;
            float v3 = ws.x * f0h.y + ws.y * f1h.y + ws.z * f2h.y + ws.w * f3h.y;
            __half2 hp0; hp0.x = __float2half_rn(v0); hp0.y = __float2half_rn(v1);
            __half2 hp1; hp1.x = __float2half_rn(v2); hp1.y = __float2half_rn(v3);
            uint2 ph; ph.x = *(unsigned*)&hp0; ph.y = *(unsigned*)&hp1;
            *(uint2*)&As[m * PAD + q * 4] = ph;
        }
        #pragma unroll
        for (int j = 0; j < 2; j++) {
            int idx = tid + 512 * j;   // 0..1023
            int n = idx >> 2;
            int part = idx & 3;
            uint4 v = *(const uint4*)&g_wth[(size_t)n * CI + part * 8];
            *(uint4*)&Bs[n * PAD + part * 8] = v;
        }
    }
    __syncthreads();

    for (int s = 0; s < STEPS; s++) {
        int cur = s & 1, nxt = cur ^ 1;
        int tap = s >> 3;

        // prefetch next tap's metadata (parity-buffered)
        if ((s & 7) == 0 && tap + 1 < KK) {
            int p = (tap + 1) & 1;
            if (tid < 128)      SB[p * 128 + tid] = g_mbase[(m_base + tid) * KK + tap + 1];
            else if (tid < 256) SW[p * 128 + tid - 128] = g_mw[(m_base + tid - 128) * KK + tap + 1];
        }

        // build step s+1 into buffers [nxt]
        if (s + 1 < STEPS) {
            int s1 = s + 1;
            int tap1 = s1 >> 3;
            int c01 = (s1 & 7) * 32;
            const int4*   SBt = SB + (tap1 & 1) * 128;
            const float4* SWt = SW + (tap1 & 1) * 128;
            __half* ah = As + nxt * AS_ELEMS;
            #pragma unroll
            for (int j = 0; j < 2; j++) {
                int task = tid + 512 * j;
                int q = task & 7;
                int m = task >> 3;
                int4 bs = SBt[m];
                float4 ws = SWt[m];
                int c = c01 + q * 4;
                uint2 r0 = *(const uint2*)&g_xt[bs.x + c];
                uint2 r1 = *(const uint2*)&g_xt[bs.y + c];
                uint2 r2 = *(const uint2*)&g_xt[bs.z + c];
                uint2 r3 = *(const uint2*)&g_xt[bs.w + c];
                float2 f0l = h2f2(r0.x), f0h = h2f2(r0.y);
                float2 f1l = h2f2(r1.x), f1h = h2f2(r1.y);
                float2 f2l = h2f2(r2.x), f2h = h2f2(r2.y);
                float2 f3l = h2f2(r3.x), f3h = h2f2(r3.y);
                float v0 = ws.x * f0l.x + ws.y * f1l.x + ws.z * f2l.x + ws.w * f3l.x;
                float v1 = ws.x * f0l.y + ws.y * f1l.y + ws.z * f2l.y + ws.w * f3l.y;
                float v2 = ws.x * f0h.x + ws.y * f1h.x + ws.z * f2h.x + ws.w * f3h.x;
                float v3 = ws.x * f0h.y + ws.y * f1h.y + ws.z * f2h.y + ws.w * f3h.y;
                __half2 hp0; hp0.x = __float2half_rn(v0); hp0.y = __float2half_rn(v1);
                __half2 hp1; hp1.x = __float2half_rn(v2); hp1.y = __float2half_rn(v3);
                uint2 ph; ph.x = *(unsigned*)&hp0; ph.y = *(unsigned*)&hp1;
                *(uint2*)&ah[m * PAD + q * 4] = ph;
            }
            const __half* wb = g_wth + (size_t)tap1 * CO * CI + c01;
            __half* bsm = Bs + nxt * BS_ELEMS;
            #pragma unroll
            for (int j = 0; j < 2; j++) {
                int idx = tid + 512 * j;
                int n = idx >> 2;
                int part = idx & 3;
                uint4 v = *(const uint4*)&wb[(size_t)n * CI + part * 8];
                *(uint4*)&bsm[n * PAD + part * 8] = v;
            }
        }

        // mma on buffers [cur]
        {
            unsigned ab = as_base + cur * (AS_ELEMS * 2);
            unsigned bb_base = bs_base + cur * (BS_ELEMS * 2) + (unsigned)(wn * 64) * (PAD * 2) + b_lane_off;
            #pragma unroll
            for (int ks = 0; ks < 2; ks++) {
                unsigned a[2][4];
                #pragma unroll
                for (int mf = 0; mf < 2; mf++) {
                    unsigned row = (unsigned)(wm * 32 + mf * 16) + a_row;
                    unsigned boff = row * (PAD * 2) + (ks * 16 + a_koff) * 2;
                    ldmat_x4(a[mf], ab + boff);
                }
                #pragma unroll
                for (int nf2 = 0; nf2 < 4; nf2++) {
                    unsigned bb4[4];
                    ldmat_x4(bb4, bb_base + (unsigned)(nf2 * 16) * (PAD * 2) + (unsigned)(ks * 32));
                    #pragma unroll
                    for (int mf = 0; mf < 2; mf++) {
                        mma_f16(acc[mf][nf2 * 2],     a[mf], bb4);
                        mma_f16(acc[mf][nf2 * 2 + 1], a[mf], bb4 + 2);
                    }
                }
            }
        }
        __syncthreads();
    }

    // ---- epilogue: BN(+bias) + ReLU, write NCHW ----
    int g = lane >> 2;
    int cq = (lane & 3) * 2;
    #pragma unroll
    for (int mf = 0; mf < 2; mf++) {
        int row0 = m_base + wm * 32 + mf * 16 + g;
        #pragma unroll
        for (int half = 0; half < 2; half++) {
            int m = row0 + half * 8;
            int b = m >> 12, h = (m >> 6) & 63, w = m & 63;
            float* orow = out + ((size_t)b * CO * HN + h) * WN + w;
            #pragma unroll
            for (int nf = 0; nf < 8; nf++) {
                int nl0 = wn * 64 + nf * 8 + cq;
                #pragma unroll
                for (int j = 0; j < 2; j++) {
                    int nl = nl0 + j;
                    float v = acc[mf][nf][half * 2 + j] * s_scale[nl] + s_shift[nl];
                    orow[(size_t)nl * HN * WN] = fmaxf(v, 0.f);
                }
            }
        }
    }
}

// ---------------- launch ----------------
#define KMAIN_SMEM (2*AS_ELEMS*2 + 2*BS_ELEMS*2 + 2*128*16 + 2*128*16 + 2*256*4)

extern "C" void kernel_launch(void* const* d_in, const int* in_sizes, int n_in,
                              void* d_out, int out_size) {
    const float* x      = (const float*)d_in[0];
    const float* w_off  = (const float*)d_in[1];
    const float* b_off  = (const float*)d_in[2];
    const float* weight = (const float*)d_in[3];
    const float* bias   = (const float*)d_in[4];
    const float* gamma  = (const float*)d_in[5];
    const float* beta   = (const float*)d_in[6];
    const float* rmean  = (const float*)d_in[7];
    const float* rvar   = (const float*)d_in[8];
    float* out = (float*)d_out;

    static bool attr_done = false;
    if (!attr_done) {
        cudaFuncSetAttribute(k_main, cudaFuncAttributeMaxDynamicSharedMemorySize, KMAIN_SMEM);
        attr_done = true;
    }

    dim3 tgrid(HN * WN / 32, CI / 32, BN_);
    k_transpose_x<<<tgrid, dim3(32, 8)>>>(x);
    k_prep_w<<<256, 256>>>(w_off, weight);
    k_offconv<<<BN_ * HN, 256>>>(b_off);
    k_main<<<BN_ * HN * WN / 128, 512, KMAIN_SMEM>>>(bias, gamma, beta, rmean, rvar, out);
}

// round 9
// speedup vs baseline: 7.0867x; 1.1499x over previous
#include <cuda_runtime.h>
#include <cuda_fp16.h>
#include <math.h>

#define BN_ 4
#define CI 256
#define CO 256
#define HN 64
#define WN 64
#define KK 9
#define EPS 1e-5f
#define PAD 40

// ---------------- scratch (device globals; no allocation) ----------------
__device__ __half g_xt[BN_*HN*WN*CI];       // x transposed to [b][y][x][c], fp16
__device__ __half g_woffh[KK*32*CI];        // offset weights fp16 [tap][o(pad32)][c]
__device__ __half g_wth[KK*CO*CI];          // main weights fp16 [tap][o][c]
__device__ int4   g_mbase[BN_*HN*WN*KK];    // 4 corner base indices into g_xt
__device__ float4 g_mw[BN_*HN*WN*KK];       // 4 corner weights (mask*valid premult)

static __device__ __forceinline__ unsigned smem_u32(const void* p) {
    return (unsigned)__cvta_generic_to_shared(p);
}

static __device__ __forceinline__ void mma_f16(float* c, const unsigned* a, const unsigned* b) {
    asm volatile(
        "mma.sync.aligned.m16n8k16.row.col.f32.f16.f16.f32 "
        "{%0,%1,%2,%3}, {%4,%5,%6,%7}, {%8,%9}, {%0,%1,%2,%3};"
        : "+f"(c[0]), "+f"(c[1]), "+f"(c[2]), "+f"(c[3])
        : "r"(a[0]), "r"(a[1]), "r"(a[2]), "r"(a[3]), "r"(b[0]), "r"(b[1]));
}

static __device__ __forceinline__ void ldmat_x4(unsigned* r, unsigned addr) {
    asm volatile("ldmatrix.sync.aligned.m8n8.x4.shared.b16 {%0,%1,%2,%3}, [%4];"
                 : "=r"(r[0]), "=r"(r[1]), "=r"(r[2]), "=r"(r[3]) : "r"(addr));
}

static __device__ __forceinline__ void cp_async16(unsigned dst, const void* src) {
    asm volatile("cp.async.cg.shared.global [%0], [%1], 16;" :: "r"(dst), "l"(src));
}
static __device__ __forceinline__ void cp_async_commit() {
    asm volatile("cp.async.commit_group;");
}
static __device__ __forceinline__ void cp_async_wait0() {
    asm volatile("cp.async.wait_group 0;" ::: "memory");
}

static __device__ __forceinline__ float2 h2f2(unsigned u) {
    return __half22float2(*reinterpret_cast<const __half2*>(&u));
}

// ---------------- T1: NCHW fp32 -> NHWC fp16 transpose of x ----------------
__global__ void k_transpose_x(const float* __restrict__ x) {
    __shared__ float tile[32][33];
    int b  = blockIdx.z;
    int c0 = blockIdx.y * 32;
    int p0 = blockIdx.x * 32;
    int tx = threadIdx.x, ty = threadIdx.y;
    const float* xb = x + (size_t)b * CI * HN * WN;
    #pragma unroll
    for (int j = 0; j < 32; j += 8)
        tile[ty + j][tx] = xb[(c0 + ty + j) * (HN * WN) + p0 + tx];
    __syncthreads();
    __half* xtb = g_xt + (size_t)b * HN * WN * CI;
    #pragma unroll
    for (int j = 0; j < 32; j += 8)
        xtb[(p0 + ty + j) * CI + c0 + tx] = __float2half_rn(tile[tx][ty + j]);
}

// ---------------- T2: weight re-layouts (fp16) ----------------
__global__ void k_prep_w(const float* __restrict__ w_off, const float* __restrict__ weight) {
    int stride = gridDim.x * blockDim.x;
    int tid = blockIdx.x * blockDim.x + threadIdx.x;
    for (int i = tid; i < KK * 32 * CI; i += stride) {
        int c = i & 255; int to = i >> 8; int o = to & 31; int tap = to >> 5;
        float v = (o < 27) ? w_off[(o * CI + c) * KK + tap] : 0.f;
        g_woffh[i] = __float2half_rn(v);
    }
    for (int i = tid; i < KK * CO * CI; i += stride) {
        int c = i & 255; int to = i >> 8; int o = to & 255; int tap = to >> 8;
        g_wth[i] = __float2half_rn(weight[(o * CI + c) * KK + tap]);
    }
}

// ---------------- O: offset conv (tensor GEMM) + fused sampling metadata ----------------
__global__ __launch_bounds__(256) void k_offconv(const float* __restrict__ b_off) {
    __shared__ __align__(16) __half As[64 * PAD];
    __shared__ __align__(16) __half Bs[32 * PAD];
    __shared__ float som[64][32];
    int row = blockIdx.x;            // b*64+h
    int b = row >> 6, h = row & 63;
    int tid = threadIdx.x;
    int lane = tid & 31;
    int wid = tid >> 5;
    int wm = wid & 3;
    int wn = wid >> 2;

    float acc[2][4];
    #pragma unroll
    for (int i = 0; i < 2; i++)
        #pragma unroll
        for (int j = 0; j < 4; j++) acc[i][j] = 0.f;

    unsigned a_row = (unsigned)(lane & 15);
    unsigned a_koff = (unsigned)((lane >> 4) * 8);
    unsigned as_base = smem_u32(As);
    unsigned bs_base = smem_u32(Bs);
    unsigned b_lane_off;
    {
        int t = lane >> 3, r = lane & 7;
        b_lane_off = (unsigned)(((t >> 1) * 8 + r) * (PAD * 2) + (t & 1) * 16);
    }

    for (int tap = 0; tap < KK; tap++) {
        int ky = tap / 3 - 1, kx = tap % 3 - 1;
        int y = h + ky;
        bool yok = (y >= 0 && y < HN);
        const __half* xrow = g_xt + ((size_t)(b * HN + (yok ? y : 0)) * WN) * CI;
        for (int c0 = 0; c0 < CI; c0 += 32) {
            __syncthreads();
            #pragma unroll
            for (int j = 0; j < 2; j++) {
                int task = tid + 256 * j;
                int q = task & 7;
                int m = task >> 3;
                int xx = m + kx;
                uint2 p = make_uint2(0u, 0u);
                if (yok && xx >= 0 && xx < WN)
                    p = *(const uint2*)&xrow[xx * CI + c0 + q * 4];
                *(uint2*)&As[m * PAD + q * 4] = p;
            }
            if (tid < 128) {
                int n = tid >> 2, part = tid & 3;
                uint4 v = *(const uint4*)&g_woffh[((size_t)(tap * 32 + n)) * CI + c0 + part * 8];
                *(uint4*)&Bs[n * PAD + part * 8] = v;
            }
            __syncthreads();
            #pragma unroll
            for (int ks = 0; ks < 2; ks++) {
                unsigned a[4];
                unsigned boff = (wm * 16 + a_row) * (PAD * 2) + (ks * 16 + a_koff) * 2;
                ldmat_x4(a, as_base + boff);
                unsigned bb4[4];
                ldmat_x4(bb4, bs_base + (unsigned)(wn * 16) * (PAD * 2) + (unsigned)(ks * 32) + b_lane_off);
                mma_f16(acc[0], a, bb4);
                mma_f16(acc[1], a, bb4 + 2);
            }
        }
    }
    {
        int g = lane >> 2;
        int cq = (lane & 3) * 2;
        #pragma unroll
        for (int nf = 0; nf < 2; nf++) {
            #pragma unroll
            for (int half = 0; half < 2; half++) {
                int m = wm * 16 + half * 8 + g;
                #pragma unroll
                for (int j = 0; j < 2; j++) {
                    int n = wn * 16 + nf * 8 + cq + j;
                    som[m][n] = acc[nf][half * 2 + j];
                }
            }
        }
    }
    __syncthreads();
    for (int idx = tid; idx < 64 * KK; idx += 256) {
        int k = idx % KK; int w = idx / KK;
        float dy = som[w][k]      + b_off[k];
        float dx = som[w][9 + k]  + b_off[9 + k];
        float mm = som[w][18 + k] + b_off[18 + k];
        float mask = 1.f / (1.f + expf(-mm));
        float py = (float)h + (float)(k / 3 - 1) + dy;
        float px = (float)w + (float)(k % 3 - 1) + dx;
        float y0f = floorf(py), x0f = floorf(px);
        float ly = py - y0f, lx = px - x0f;
        int y0 = (int)y0f, x0 = (int)x0f;
        int y1 = y0 + 1, x1 = x0 + 1;
        float vy0 = (y0 >= 0 && y0 < HN) ? 1.f : 0.f;
        float vy1 = (y1 >= 0 && y1 < HN) ? 1.f : 0.f;
        float vx0 = (x0 >= 0 && x0 < WN) ? 1.f : 0.f;
        float vx1 = (x1 >= 0 && x1 < WN) ? 1.f : 0.f;
        int yc0 = min(max(y0, 0), HN - 1), yc1 = min(max(y1, 0), HN - 1);
        int xc0 = min(max(x0, 0), WN - 1), xc1 = min(max(x1, 0), WN - 1);
        float4 wv;
        wv.x = (1.f - ly) * (1.f - lx) * mask * vy0 * vx0;
        wv.y = (1.f - ly) * lx         * mask * vy0 * vx1;
        wv.z = ly * (1.f - lx)         * mask * vy1 * vx0;
        wv.w = ly * lx                 * mask * vy1 * vx1;
        int bb = b * HN * WN;
        int4 bv;
        bv.x = (bb + yc0 * WN + xc0) * CI;
        bv.y = (bb + yc0 * WN + xc1) * CI;
        bv.z = (bb + yc1 * WN + xc0) * CI;
        bv.w = (bb + yc1 * WN + xc1) * CI;
        int gidx = (row * 64 + w) * KK + k;
        g_mbase[gidx] = bv;
        g_mw[gidx] = wv;
    }
}

// ---------------- G: fused sample + fp16 GEMM, BM=128 BN=256, latency-hiding pipeline ---
#define AS_ELEMS (128 * PAD)
#define BS_ELEMS (256 * PAD)
#define STEPS 72   // 9 taps * 8 c0-chunks

__global__ __launch_bounds__(512, 1) void k_main(const float* __restrict__ bias,
                                              const float* __restrict__ gamma,
                                              const float* __restrict__ beta,
                                              const float* __restrict__ rmean,
                                              const float* __restrict__ rvar,
                                              float* __restrict__ out) {
    extern __shared__ __align__(16) char dyn[];
    __half* As    = (__half*)dyn;                         // [2][AS_ELEMS]
    __half* Bs    = As + 2 * AS_ELEMS;                    // [2][BS_ELEMS]
    int4*   SB    = (int4*)(Bs + 2 * BS_ELEMS);           // [2][128]
    float4* SW    = (float4*)(SB + 2 * 128);              // [2][128]
    float*  s_scale = (float*)(SW + 2 * 128);             // [256]
    float*  s_shift = s_scale + 256;                      // [256]

    int m_base = blockIdx.x * 128;
    int tid = threadIdx.x;
    int lane = tid & 31;
    int wid = tid >> 5;
    int wm = wid & 3;          // m-warp: 32 rows
    int wn = wid >> 2;         // n-warp 0..3: 64 cols

    if (tid < 256) {
        float inv = gamma[tid] * rsqrtf(rvar[tid] + EPS);
        s_scale[tid] = inv;
        s_shift[tid] = beta[tid] - rmean[tid] * inv + bias[tid] * inv;
    }
    if (tid < 128)      SB[tid] = g_mbase[(m_base + tid) * KK + 0];
    else if (tid < 256) SW[tid - 128] = g_mw[(m_base + tid - 128) * KK + 0];
    __syncthreads();

    float acc[2][8][4];
    #pragma unroll
    for (int i = 0; i < 2; i++)
        #pragma unroll
        for (int j = 0; j < 8; j++)
            #pragma unroll
            for (int q = 0; q < 4; q++) acc[i][j][q] = 0.f;

    unsigned a_row = (unsigned)(lane & 15);
    unsigned a_koff = (unsigned)((lane >> 4) * 8);
    unsigned as_base = smem_u32(As);
    unsigned bs_base = smem_u32(Bs);
    unsigned b_lane_off;
    {
        int t = lane >> 3, r = lane & 7;
        b_lane_off = (unsigned)(((t >> 1) * 8 + r) * (PAD * 2) + (t & 1) * 16);
    }

    // one gather task per thread: m = tid>>2 (0..127), q-oct = tid&3 (8 channels)
    const int tk_m = tid >> 2;
    const int tk_q = (tid & 3) * 8;
    const int as_off = tk_m * PAD + tk_q;      // halfs
    // B cp.async task: n = tid>>1 (0..255)? 512 thr * 2 iters of 16B = 16KB
    // iter j: idx = tid + 512*j; n = idx>>2, part = idx&3

    // ---- build step 0 into buffer 0 (blocking) ----
    {
        int4 bs = SB[tk_m];
        float4 ws = SW[tk_m];
        uint4 r0 = *(const uint4*)&g_xt[bs.x + tk_q];
        uint4 r1 = *(const uint4*)&g_xt[bs.y + tk_q];
        uint4 r2 = *(const uint4*)&g_xt[bs.z + tk_q];
        uint4 r3 = *(const uint4*)&g_xt[bs.w + tk_q];
        float2 v[4];
        #pragma unroll
        for (int p = 0; p < 4; p++) {
            unsigned u0 = (&r0.x)[p], u1 = (&r1.x)[p], u2 = (&r2.x)[p], u3 = (&r3.x)[p];
            float2 f0 = h2f2(u0), f1 = h2f2(u1), f2 = h2f2(u2), f3 = h2f2(u3);
            v[p].x = ws.x * f0.x + ws.y * f1.x + ws.z * f2.x + ws.w * f3.x;
            v[p].y = ws.x * f0.y + ws.y * f1.y + ws.z * f2.y + ws.w * f3.y;
        }
        uint4 o;
        #pragma unroll
        for (int p = 0; p < 4; p++) {
            __half2 hp; hp.x = __float2half_rn(v[p].x); hp.y = __float2half_rn(v[p].y);
            (&o.x)[p] = *(unsigned*)&hp;
        }
        *(uint4*)&As[as_off] = o;
        #pragma unroll
        for (int j = 0; j < 2; j++) {
            int idx = tid + 512 * j;
            int n = idx >> 2;
            int part = idx & 3;
            uint4 vv = *(const uint4*)&g_wth[(size_t)n * CI + part * 8];
            *(uint4*)&Bs[n * PAD + part * 8] = vv;
        }
    }
    __syncthreads();

    for (int s = 0; s < STEPS; s++) {
        int cur = s & 1, nxt = cur ^ 1;
        int tap = s >> 3;

        // prefetch next tap's metadata (parity-buffered)
        if ((s & 7) == 0 && tap + 1 < KK) {
            int p = (tap + 1) & 1;
            if (tid < 128)      SB[p * 128 + tid] = g_mbase[(m_base + tid) * KK + tap + 1];
            else if (tid < 256) SW[p * 128 + tid - 128] = g_mw[(m_base + tid - 128) * KK + tap + 1];
        }

        bool have_next = (s + 1 < STEPS);
        uint4 r0, r1, r2, r3;
        float4 ws;
        // ---- phase 1: issue gather LDGs for step s+1 into registers ----
        if (have_next) {
            int s1 = s + 1;
            int tap1 = s1 >> 3;
            int c01 = (s1 & 7) * 32;
            int4 bs = SB[(tap1 & 1) * 128 + tk_m];
            ws = SW[(tap1 & 1) * 128 + tk_m];
            int c = c01 + tk_q;
            r0 = *(const uint4*)&g_xt[bs.x + c];
            r1 = *(const uint4*)&g_xt[bs.y + c];
            r2 = *(const uint4*)&g_xt[bs.z + c];
            r3 = *(const uint4*)&g_xt[bs.w + c];
            // ---- phase 2: cp.async B tile for s+1 (reg-free) ----
            const __half* wb = g_wth + (size_t)tap1 * CO * CI + c01;
            unsigned bdst = bs_base + (unsigned)(nxt * BS_ELEMS * 2);
            #pragma unroll
            for (int j = 0; j < 2; j++) {
                int idx = tid + 512 * j;
                int n = idx >> 2;
                int part = idx & 3;
                cp_async16(bdst + (unsigned)(n * PAD + part * 8) * 2, &wb[(size_t)n * CI + part * 8]);
            }
            cp_async_commit();
        }

        // ---- phase 3: mma on buffers [cur] (covers in-flight LDG/LDGSTS) ----
        {
            unsigned ab = as_base + cur * (AS_ELEMS * 2);
            unsigned bb_base = bs_base + cur * (BS_ELEMS * 2) + (unsigned)(wn * 64) * (PAD * 2) + b_lane_off;
            #pragma unroll
            for (int ks = 0; ks < 2; ks++) {
                unsigned a[2][4];
                #pragma unroll
                for (int mf = 0; mf < 2; mf++) {
                    unsigned row = (unsigned)(wm * 32 + mf * 16) + a_row;
                    unsigned boff = row * (PAD * 2) + (ks * 16 + a_koff) * 2;
                    ldmat_x4(a[mf], ab + boff);
                }
                #pragma unroll
                for (int nf2 = 0; nf2 < 4; nf2++) {
                    unsigned bb4[4];
                    ldmat_x4(bb4, bb_base + (unsigned)(nf2 * 16) * (PAD * 2) + (unsigned)(ks * 32));
                    #pragma unroll
                    for (int mf = 0; mf < 2; mf++) {
                        mma_f16(acc[mf][nf2 * 2],     a[mf], bb4);
                        mma_f16(acc[mf][nf2 * 2 + 1], a[mf], bb4 + 2);
                    }
                }
            }
        }

        // ---- phase 4: blend + convert + store A for s+1; drain cp.async ----
        if (have_next) {
            float2 v[4];
            #pragma unroll
            for (int p = 0; p < 4; p++) {
                unsigned u0 = (&r0.x)[p], u1 = (&r1.x)[p], u2 = (&r2.x)[p], u3 = (&r3.x)[p];
                float2 f0 = h2f2(u0), f1 = h2f2(u1), f2 = h2f2(u2), f3 = h2f2(u3);
                v[p].x = ws.x * f0.x + ws.y * f1.x + ws.z * f2.x + ws.w * f3.x;
                v[p].y = ws.x * f0.y + ws.y * f1.y + ws.z * f2.y + ws.w * f3.y;
            }
            uint4 o;
            #pragma unroll
            for (int p = 0; p < 4; p++) {
                __half2 hp; hp.x = __float2half_rn(v[p].x); hp.y = __float2half_rn(v[p].y);
                (&o.x)[p] = *(unsigned*)&hp;
            }
            *(uint4*)&As[nxt * AS_ELEMS + as_off] = o;
            cp_async_wait0();
        }
        __syncthreads();
    }

    // ---- epilogue: BN(+bias) + ReLU, write NCHW ----
    int g = lane >> 2;
    int cq = (lane & 3) * 2;
    #pragma unroll
    for (int mf = 0; mf < 2; mf++) {
        int row0 = m_base + wm * 32 + mf * 16 + g;
        #pragma unroll
        for (int half = 0; half < 2; half++) {
            int m = row0 + half * 8;
            int b = m >> 12, h = (m >> 6) & 63, w = m & 63;
            float* orow = out + ((size_t)b * CO * HN + h) * WN + w;
            #pragma unroll
            for (int nf = 0; nf < 8; nf++) {
                int nl0 = wn * 64 + nf * 8 + cq;
                #pragma unroll
                for (int j = 0; j < 2; j++) {
                    int nl = nl0 + j;
                    float v = acc[mf][nf][half * 2 + j] * s_scale[nl] + s_shift[nl];
                    orow[(size_t)nl * HN * WN] = fmaxf(v, 0.f);
                }
            }
        }
    }
}

// ---------------- launch ----------------
#define KMAIN_SMEM (2*AS_ELEMS*2 + 2*BS_ELEMS*2 + 2*128*16 + 2*128*16 + 2*256*4)

extern "C" void kernel_launch(void* const* d_in, const int* in_sizes, int n_in,
                              void* d_out, int out_size) {
    const float* x      = (const float*)d_in[0];
    const float* w_off  = (const float*)d_in[1];
    const float* b_off  = (const float*)d_in[2];
    const float* weight = (const float*)d_in[3];
    const float* bias   = (const float*)d_in[4];
    const float* gamma  = (const float*)d_in[5];
    const float* beta   = (const float*)d_in[6];
    const float* rmean  = (const float*)d_in[7];
    const float* rvar   = (const float*)d_in[8];
    float* out = (float*)d_out;

    static bool attr_done = false;
    if (!attr_done) {
        cudaFuncSetAttribute(k_main, cudaFuncAttributeMaxDynamicSharedMemorySize, KMAIN_SMEM);
        attr_done = true;
    }

    dim3 tgrid(HN * WN / 32, CI / 32, BN_);
    k_transpose_x<<<tgrid, dim3(32, 8)>>>(x);
    k_prep_w<<<256, 256>>>(w_off, weight);
    k_offconv<<<BN_ * HN, 256>>>(b_off);
    k_main<<<BN_ * HN * WN / 128, 512, KMAIN_SMEM>>>(bias, gamma, beta, rmean, rvar, out);
}